// round 10
// baseline (speedup 1.0000x reference)
#include <cuda_runtime.h>
#include <cstdint>

#define B_ 8
#define L_ 8192
#define H_ 128
#define N_ 32
#define G_ 256   /* 2H */
#define TC 64    /* chunk length */
#define J_ 128   /* chunks per sequence */

typedef unsigned long long ull;

// Scratch (static __device__ arrays: no allocation anywhere)
__device__ float4 g_wk[H_ * N_];                        // {w_re, w_im, k_re, k_im}
__device__ float2 g_wT[H_ * N_];                        // w^64
__device__ __align__(16) float g_A1f[(size_t)H_ * TC * TC];      // finals matrix [h][k][r]
__device__ __align__(16) float g_A2f[(size_t)H_ * 2 * TC * TC];  // [Tri+D | V]   [h][k][t]
__device__ float  g_y[(size_t)B_ * H_ * L_];            // post-GELU activations (B,H,L)
__device__ __align__(16) float g_wtf[H_ * G_];          // out_w transposed: [k][g] plain
__device__ float  g_pooled[B_ * H_];

__device__ __forceinline__ ull fma2(ull a, ull b, ull c) {
    ull d; asm("fma.rn.f32x2 %0,%1,%2,%3;" : "=l"(d) : "l"(a), "l"(b), "l"(c)); return d;
}
__device__ __forceinline__ ull pack2(float x, float y) {
    ull d; asm("mov.b64 %0,{%1,%2};" : "=l"(d) : "f"(x), "f"(y)); return d;
}
__device__ __forceinline__ float2 unpack2(ull a) {
    float2 r; asm("mov.b64 {%0,%1},%2;" : "=f"(r.x), "=f"(r.y) : "l"(a)); return r;
}
__device__ __forceinline__ float gelu_f(float yv) {
    float c_ = fmaf(0.044715f, yv * yv, 1.f);
    float q_ = -1.5957691216f * yv * c_;
    return __fdividef(yv, 1.f + __expf(q_));            // yv * sigmoid(2*0.79788*yv*c)
}

// ---------------------------------------------------------------------------
// Setup 1: SSM params + w^64; transpose out_w; zero pooled. 32768 thr.
// ---------------------------------------------------------------------------
__global__ void setup_kernel(const float* __restrict__ log_dt,
                             const float* __restrict__ log_A_real,
                             const float* __restrict__ A_imag,
                             const float* __restrict__ C_re,
                             const float* __restrict__ C_im,
                             const float* __restrict__ out_w) {
    int i = blockIdx.x * blockDim.x + threadIdx.x;      // 0..32767
    {   // out_w row-major (2H,H): element [g][k] -> g_wtf[k][g]
        int g = i & 255, k = i >> 8;
        g_wtf[k * G_ + g] = out_w[g * H_ + k];
    }
    if (i < H_ * N_) {
        int h = i >> 5;
        float dt = expf(log_dt[h]);
        float ar = -expf(log_A_real[i]);
        float ai = A_imag[i];
        float er = expf(dt * ar);
        float si, co;
        sincosf(dt * ai, &si, &co);
        float wr = er * co, wi = er * si;       // w = exp(dt*A)
        float inv = 1.f / (ar * ar + ai * ai);
        float dr = wr - 1.f;
        float qr = (dr * ar + wi * ai) * inv;   // (w-1)/A
        float qi = (wi * ar - dr * ai) * inv;
        float cr = C_re[i], ci = C_im[i];
        float kr = 2.f * (cr * qr - ci * qi);   // k = 2*C*(w-1)/A
        float ki = 2.f * (cr * qi + ci * qr);
        g_wk[i] = make_float4(wr, wi, kr, ki);
        float tr = wr, ti = wi;                  // w^64 by 6 squarings
        #pragma unroll
        for (int s = 0; s < 6; ++s) {
            float nr = tr * tr - ti * ti;
            ti = 2.f * tr * ti;
            tr = nr;
        }
        g_wT[i] = make_float2(tr, ti);
    }
    if (i < B_ * H_) g_pooled[i] = 0.f;
}

// ---------------------------------------------------------------------------
// Setup 2: per-head matrices (plain floats, row-major [k][r]).
// ---------------------------------------------------------------------------
__global__ void setup2_kernel(const float* __restrict__ D) {
    __shared__ float wr[TC + 1][32], wim[TC + 1][32];
    __shared__ float skr[32], ski[32], kap[TC];
    int h = blockIdx.x, t = threadIdx.x;
    if (t < 32) {
        float4 wk = g_wk[h * N_ + t];
        skr[t] = wk.z; ski[t] = wk.w;
        float cr = 1.f, ci = 0.f;
        for (int d = 0; d <= TC; ++d) {
            wr[d][t] = cr; wim[d][t] = ci;
            float nr = cr * wk.x - ci * wk.y;
            ci = cr * wk.y + ci * wk.x;
            cr = nr;
        }
    }
    __syncthreads();
    {   // kappa[t] = Re(sum_n k_n w_n^t)
        float s = 0.f;
        #pragma unroll
        for (int n = 0; n < 32; ++n)
            s += skr[n] * wr[t][n] - ski[n] * wim[t][n];
        kap[t] = s;
    }
    __syncthreads();
    float Dh = D[h];
    for (int idx = t; idx < TC * TC; idx += 64) {
        int k = idx >> 6, r = idx & 63, n = r & 31;
        g_A1f[((size_t)h * TC + k) * TC + r] = (r < 32) ? wr[63 - k][n] : wim[63 - k][n];
    }
    for (int idx = t; idx < 2 * TC * TC; idx += 64) {
        int k = idx >> 6, tt = idx & 63;
        float v;
        if (k < 64)      v = (tt > k) ? kap[tt - k] : (tt == k ? kap[0] + Dh : 0.f);
        else if (k < 96) { int n = k - 64; v = skr[n] * wr[tt + 1][n] - ski[n] * wim[tt + 1][n]; }
        else             { int n = k - 96; v = -(skr[n] * wim[tt + 1][n] + ski[n] * wr[tt + 1][n]); }
        g_A2f[((size_t)h * 2 * TC + k) * TC + tt] = v;
    }
}

// ---------------------------------------------------------------------------
// Fused SSM (unchanged from R8): block = (h, b), 196 KB dyn smem.
// ---------------------------------------------------------------------------
#define SB_STRIDE 130      /* ull stride, even -> 16B-aligned rows */
#define SFC_STRIDE 68
#define SMEM_BYTES 200704  /* 32768 (A) + 133120 (sB) + 34816 (sFC) */

#define GBODY {                                                              \
    ulonglong2 a = *reinterpret_cast<const ulonglong2*>(ap);                 \
    ulonglong2 u01 = *reinterpret_cast<const ulonglong2*>(up);               \
    ulonglong2 u23 = *reinterpret_cast<const ulonglong2*>(up + 2);           \
    ulonglong2 u45 = *reinterpret_cast<const ulonglong2*>(up + 4);           \
    ulonglong2 u67 = *reinterpret_cast<const ulonglong2*>(up + 6);           \
    acc[0][0]=fma2(a.x,u01.x,acc[0][0]); acc[1][0]=fma2(a.y,u01.x,acc[1][0]);\
    acc[0][1]=fma2(a.x,u01.y,acc[0][1]); acc[1][1]=fma2(a.y,u01.y,acc[1][1]);\
    acc[0][2]=fma2(a.x,u23.x,acc[0][2]); acc[1][2]=fma2(a.y,u23.x,acc[1][2]);\
    acc[0][3]=fma2(a.x,u23.y,acc[0][3]); acc[1][3]=fma2(a.y,u23.y,acc[1][3]);\
    acc[0][4]=fma2(a.x,u45.x,acc[0][4]); acc[1][4]=fma2(a.y,u45.x,acc[1][4]);\
    acc[0][5]=fma2(a.x,u45.y,acc[0][5]); acc[1][5]=fma2(a.y,u45.y,acc[1][5]);\
    acc[0][6]=fma2(a.x,u67.x,acc[0][6]); acc[1][6]=fma2(a.y,u67.x,acc[1][6]);\
    acc[0][7]=fma2(a.x,u67.y,acc[0][7]); acc[1][7]=fma2(a.y,u67.y,acc[1][7]);\
    ap += TC; up += SB_STRIDE;                                               \
}

__global__ void __launch_bounds__(256) ssm_kernel(const float* __restrict__ x,
                                                  const float* __restrict__ enc_w,
                                                  const float* __restrict__ enc_b) {
    extern __shared__ char smem[];
    float* sA  = reinterpret_cast<float*>(smem);                 // [k][64 r/t]
    ull*   sB  = reinterpret_cast<ull*>(smem + 32768);           // [k][128 col] dup'd
    float* sFC = reinterpret_cast<float*>(smem + 165888);        // [col][64 r]
    int tid = threadIdx.x;
    int tx = tid & 15, ty = tid >> 4;    // rows 4tx..4tx+3, cols 8ty..8ty+7
    int h = blockIdx.x >> 3, b = blockIdx.x & 7;

    // ---- fill u (dup'd) rows 0..63 of sB; encoder fused ----
    float e0 = enc_w[h], e1 = enc_w[H_ + h], eb = enc_b[h];
    const float2* xb = reinterpret_cast<const float2*>(x) + (size_t)b * L_;
    #pragma unroll
    for (int m = tid; m < 8192; m += 256) {
        float2 xv = xb[m];
        float u = fmaf(e1, xv.y, fmaf(e0, xv.x, eb));
        sB[(size_t)(m & 63) * SB_STRIDE + (m >> 6)] = pack2(u, u);
    }
    // ---- load A1 (4096 floats) ----
    {
        const float4* A1p = reinterpret_cast<const float4*>(g_A1f + (size_t)h * TC * TC);
        float4* sA4 = reinterpret_cast<float4*>(sA);
        #pragma unroll
        for (int m = tid; m < 1024; m += 256) sA4[m] = A1p[m];
    }
    __syncthreads();

    // ---- GEMM1: F = A1 * u ----
    ull acc[2][8];
    #pragma unroll
    for (int c = 0; c < 8; ++c) { acc[0][c] = 0ull; acc[1][c] = 0ull; }
    {
        const float* ap = sA + 4 * tx;
        const ull* up = sB + 8 * ty;
        #pragma unroll 4
        for (int k = 0; k < TC; ++k) GBODY
    }
    #pragma unroll
    for (int c = 0; c < 8; ++c) {
        float2 r0 = unpack2(acc[0][c]), r1 = unpack2(acc[1][c]);
        *reinterpret_cast<float4*>(sFC + (8 * ty + c) * SFC_STRIDE + 4 * tx) =
            make_float4(r0.x, r0.y, r1.x, r1.y);
    }
    __syncthreads();

    // ---- load A2 (8192 floats) while warp 0 runs the carry chain ----
    {
        const float4* A2p = reinterpret_cast<const float4*>(g_A2f + (size_t)h * 2 * TC * TC);
        float4* sA4 = reinterpret_cast<float4*>(sA);
        #pragma unroll
        for (int m = tid; m < 2048; m += 256) sA4[m] = A2p[m];
    }
    if (tid < 32) {          // chain: c(j) = w^64 c(j-1) + f(j-1), overwrite F->C
        float2 wT = g_wT[h * N_ + tid];
        float wTx = wT.x, wTy = wT.y;
        float cr = 0.f, ci = 0.f;
        float* fr0 = sFC + tid;
        float* fi0 = sFC + 32 + tid;
        for (int j = 0; j < J_; j += 4) {
            float fr[4], fi[4];
            #pragma unroll
            for (int q = 0; q < 4; ++q) {
                fr[q] = fr0[(j + q) * SFC_STRIDE];
                fi[q] = fi0[(j + q) * SFC_STRIDE];
            }
            #pragma unroll
            for (int q = 0; q < 4; ++q) {
                fr0[(j + q) * SFC_STRIDE] = cr;
                fi0[(j + q) * SFC_STRIDE] = ci;
                float nr = fmaf(wTx, cr, fmaf(-wTy, ci, fr[q]));
                ci = fmaf(wTy, cr, fmaf(wTx, ci, fi[q]));
                cr = nr;
            }
        }
    }
    __syncthreads();

    // ---- dup carries into sB rows 64..127 ----
    #pragma unroll
    for (int m = tid; m < 8192; m += 256) {
        float v = sFC[(m >> 6) * SFC_STRIDE + (m & 63)];
        sB[(size_t)(64 + (m & 63)) * SB_STRIDE + (m >> 6)] = pack2(v, v);
    }
    __syncthreads();

    // ---- GEMM2: y = A2 * [u;c], then GELU ----
    #pragma unroll
    for (int c = 0; c < 8; ++c) { acc[0][c] = 0ull; acc[1][c] = 0ull; }
    {
        const float* ap = sA + 4 * tx;
        const ull* up = sB + 8 * ty;
        #pragma unroll 4
        for (int k = 0; k < 2 * TC; ++k) GBODY
    }
    float* yb = g_y + ((size_t)b * H_ + h) * L_;
    #pragma unroll
    for (int c = 0; c < 8; ++c) {
        int col = 8 * ty + c;
        float2 r0 = unpack2(acc[0][c]), r1 = unpack2(acc[1][c]);
        float4 o = make_float4(gelu_f(r0.x), gelu_f(r0.y), gelu_f(r1.x), gelu_f(r1.y));
        *reinterpret_cast<float4*>(yb + (size_t)col * TC + 4 * tx) = o;
    }
}

// ---------------------------------------------------------------------------
// GLU projection + pool, smem-staged (ssm_kernel recipe).
// Block = (type, b, 128-l tile). type 0: a-rows 0..63 + gates 128..191;
// type 1: a-rows 64..127 + gates 192..255.
// sW [k][128] plain floats (cols 0..63 = a, 64..127 = gate), 64 KB.
// sY [k][128 cols] dup'd f32x2, 130 KB. Thread tile: 2 a-pairs + 2 gate-pairs
// x 8 cols -> 32 fma2 + 6 LDS.128 per k, zero LDG in loop.
// ---------------------------------------------------------------------------
#define GLS 130                 /* sY ull stride */
#define GLU_SMEM 198656         /* 65536 (sW) + 133120 (sY) */

__global__ void __launch_bounds__(256) glu_kernel(const float* __restrict__ out_b) {
    extern __shared__ char smem[];
    float* sW = reinterpret_cast<float*>(smem);             // [k][128]
    ull*   sY = reinterpret_cast<ull*>(smem + 65536);       // [k][128 cols] dup'd
    int tid = threadIdx.x;
    int tx = tid & 15, ty = tid >> 4;       // a-rows 4tx..4tx+3 (+gate), cols 8ty..8ty+7
    int bidx = blockIdx.x;
    int typ = bidx & 1;
    int tile = bidx >> 1;                   // 0..511
    int b = tile >> 6, l0 = (tile & 63) << 7;
    int gofs = typ << 6;                    // 0 or 64

    // ---- stage weights: sW[k][j] = W[g][k], g = gofs+j (j<64) / 128+gofs+j-64 ----
    #pragma unroll
    for (int m = tid; m < 16384; m += 256) {
        int k = m >> 7, j = m & 127;
        int g = (j < 64) ? (gofs + j) : (128 + gofs + (j - 64));
        sW[m] = g_wtf[k * G_ + g];
    }
    // ---- stage y tile dup'd: sY[h][c] = {y,y} ----
    const float* yb = g_y + (size_t)b * H_ * L_ + l0;
    #pragma unroll
    for (int m = tid; m < 4096; m += 256) {
        int k = m >> 5, cq = (m & 31) << 2;
        float4 v = *reinterpret_cast<const float4*>(yb + (size_t)k * L_ + cq);
        ull* dst = sY + (size_t)k * GLS + cq;
        dst[0] = pack2(v.x, v.x); dst[1] = pack2(v.y, v.y);
        dst[2] = pack2(v.z, v.z); dst[3] = pack2(v.w, v.w);
    }
    __syncthreads();

    ull acc[4][8];                          // [0..1]=a-pairs, [2..3]=gate-pairs
    #pragma unroll
    for (int r = 0; r < 4; ++r)
        #pragma unroll
        for (int c = 0; c < 8; ++c) acc[r][c] = 0ull;

    {
        const float* ap = sW + 4 * tx;      // a-part; gate at +64
        const ull* up = sY + 8 * ty;
        #pragma unroll 2
        for (int k = 0; k < H_; ++k) {
            ulonglong2 a  = *reinterpret_cast<const ulonglong2*>(ap);
            ulonglong2 gg = *reinterpret_cast<const ulonglong2*>(ap + 64);
            ulonglong2 u01 = *reinterpret_cast<const ulonglong2*>(up);
            ulonglong2 u23 = *reinterpret_cast<const ulonglong2*>(up + 2);
            ulonglong2 u45 = *reinterpret_cast<const ulonglong2*>(up + 4);
            ulonglong2 u67 = *reinterpret_cast<const ulonglong2*>(up + 6);
            acc[0][0]=fma2(a.x,u01.x,acc[0][0]);  acc[1][0]=fma2(a.y,u01.x,acc[1][0]);
            acc[2][0]=fma2(gg.x,u01.x,acc[2][0]); acc[3][0]=fma2(gg.y,u01.x,acc[3][0]);
            acc[0][1]=fma2(a.x,u01.y,acc[0][1]);  acc[1][1]=fma2(a.y,u01.y,acc[1][1]);
            acc[2][1]=fma2(gg.x,u01.y,acc[2][1]); acc[3][1]=fma2(gg.y,u01.y,acc[3][1]);
            acc[0][2]=fma2(a.x,u23.x,acc[0][2]);  acc[1][2]=fma2(a.y,u23.x,acc[1][2]);
            acc[2][2]=fma2(gg.x,u23.x,acc[2][2]); acc[3][2]=fma2(gg.y,u23.x,acc[3][2]);
            acc[0][3]=fma2(a.x,u23.y,acc[0][3]);  acc[1][3]=fma2(a.y,u23.y,acc[1][3]);
            acc[2][3]=fma2(gg.x,u23.y,acc[2][3]); acc[3][3]=fma2(gg.y,u23.y,acc[3][3]);
            acc[0][4]=fma2(a.x,u45.x,acc[0][4]);  acc[1][4]=fma2(a.y,u45.x,acc[1][4]);
            acc[2][4]=fma2(gg.x,u45.x,acc[2][4]); acc[3][4]=fma2(gg.y,u45.x,acc[3][4]);
            acc[0][5]=fma2(a.x,u45.y,acc[0][5]);  acc[1][5]=fma2(a.y,u45.y,acc[1][5]);
            acc[2][5]=fma2(gg.x,u45.y,acc[2][5]); acc[3][5]=fma2(gg.y,u45.y,acc[3][5]);
            acc[0][6]=fma2(a.x,u67.x,acc[0][6]);  acc[1][6]=fma2(a.y,u67.x,acc[1][6]);
            acc[2][6]=fma2(gg.x,u67.x,acc[2][6]); acc[3][6]=fma2(gg.y,u67.x,acc[3][6]);
            acc[0][7]=fma2(a.x,u67.y,acc[0][7]);  acc[1][7]=fma2(a.y,u67.y,acc[1][7]);
            acc[2][7]=fma2(gg.x,u67.y,acc[2][7]); acc[3][7]=fma2(gg.y,u67.y,acc[3][7]);
            ap += 128; up += GLS;
        }
    }

    // ---- GLU epilogue + pool ----
    int g0 = gofs + 4 * tx;                 // a-channel base (0..127)
    float bA0 = out_b[g0], bA1 = out_b[g0 + 1], bA2 = out_b[g0 + 2], bA3 = out_b[g0 + 3];
    float bG0 = out_b[128 + g0], bG1 = out_b[128 + g0 + 1];
    float bG2 = out_b[128 + g0 + 2], bG3 = out_b[128 + g0 + 3];
    float s0 = 0.f, s1 = 0.f, s2 = 0.f, s3 = 0.f;
    #pragma unroll
    for (int c = 0; c < 8; ++c) {
        float2 a01 = unpack2(acc[0][c]);
        float2 a23 = unpack2(acc[1][c]);
        float2 q01 = unpack2(acc[2][c]);
        float2 q23 = unpack2(acc[3][c]);
        s0 += (a01.x + bA0) * __fdividef(1.f, 1.f + __expf(-(q01.x + bG0)));
        s1 += (a01.y + bA1) * __fdividef(1.f, 1.f + __expf(-(q01.y + bG1)));
        s2 += (a23.x + bA2) * __fdividef(1.f, 1.f + __expf(-(q23.x + bG2)));
        s3 += (a23.y + bA3) * __fdividef(1.f, 1.f + __expf(-(q23.y + bG3)));
    }
    float* pp = g_pooled + b * H_ + g0;
    atomicAdd(pp,     s0);
    atomicAdd(pp + 1, s1);
    atomicAdd(pp + 2, s2);
    atomicAdd(pp + 3, s3);
}

// ---------------------------------------------------------------------------
// Decode: out[b] = (pooled_sum[b,:]/L) . dec_w + dec_b
// ---------------------------------------------------------------------------
__global__ void decode_kernel(const float* __restrict__ dec_w,
                              const float* __restrict__ dec_b,
                              float* __restrict__ out) {
    int wid = threadIdx.x >> 5, lane = threadIdx.x & 31;
    int b = wid;
    float p = 0.f;
    #pragma unroll
    for (int i = 0; i < 4; i++) {
        int h = lane + 32 * i;
        p += g_pooled[b * H_ + h] * dec_w[h];
    }
    p += __shfl_xor_sync(0xffffffffu, p, 16);
    p += __shfl_xor_sync(0xffffffffu, p, 8);
    p += __shfl_xor_sync(0xffffffffu, p, 4);
    p += __shfl_xor_sync(0xffffffffu, p, 2);
    p += __shfl_xor_sync(0xffffffffu, p, 1);
    if (lane == 0) out[b] = p * (1.f / (float)L_) + dec_b[0];
}

// ---------------------------------------------------------------------------
extern "C" void kernel_launch(void* const* d_in, const int* in_sizes, int n_in,
                              void* d_out, int out_size) {
    const float* x      = (const float*)d_in[0];
    const float* enc_w  = (const float*)d_in[1];
    const float* enc_b  = (const float*)d_in[2];
    const float* log_dt = (const float*)d_in[3];
    const float* log_A  = (const float*)d_in[4];
    const float* A_im   = (const float*)d_in[5];
    const float* C_re   = (const float*)d_in[6];
    const float* C_im   = (const float*)d_in[7];
    const float* D      = (const float*)d_in[8];
    const float* out_w  = (const float*)d_in[9];
    const float* out_b  = (const float*)d_in[10];
    const float* dec_w  = (const float*)d_in[11];
    const float* dec_b  = (const float*)d_in[12];
    float* out = (float*)d_out;

    cudaFuncSetAttribute(ssm_kernel, cudaFuncAttributeMaxDynamicSharedMemorySize,
                         SMEM_BYTES);
    cudaFuncSetAttribute(glu_kernel, cudaFuncAttributeMaxDynamicSharedMemorySize,
                         GLU_SMEM);

    setup_kernel<<<128, 256>>>(log_dt, log_A, A_im, C_re, C_im, out_w);
    setup2_kernel<<<128, 64>>>(D);
    ssm_kernel<<<1024, 256, SMEM_BYTES>>>(x, enc_w, enc_b);
    glu_kernel<<<1024, 256, GLU_SMEM>>>(out_b);
    decode_kernel<<<1, 256>>>(dec_w, dec_b, out);
}

// round 12
// speedup vs baseline: 1.8866x; 1.8866x over previous
#include <cuda_runtime.h>
#include <cstdint>

#define B_ 8
#define L_ 8192
#define H_ 128
#define N_ 32
#define G_ 256   /* 2H */
#define TC 64    /* chunk length */
#define J_ 128   /* chunks per sequence */

typedef unsigned long long ull;

// Scratch (static __device__ arrays: no allocation anywhere)
__device__ float4 g_wk[H_ * N_];                        // {w_re, w_im, k_re, k_im}
__device__ float2 g_wT[H_ * N_];                        // w^64
__device__ __align__(16) float g_A1f[(size_t)H_ * TC * TC];      // finals matrix [h][k][r]
__device__ __align__(16) float g_A2f[(size_t)H_ * 2 * TC * TC];  // [Tri+D | V]   [h][k][t]
__device__ float  g_y[(size_t)B_ * H_ * L_];            // post-GELU activations (B,H,L)
__device__ float  g_pooled[B_ * H_];

__device__ __forceinline__ ull fma2(ull a, ull b, ull c) {
    ull d; asm("fma.rn.f32x2 %0,%1,%2,%3;" : "=l"(d) : "l"(a), "l"(b), "l"(c)); return d;
}
__device__ __forceinline__ ull pack2(float x, float y) {
    ull d; asm("mov.b64 %0,{%1,%2};" : "=l"(d) : "f"(x), "f"(y)); return d;
}
__device__ __forceinline__ float2 unpack2(ull a) {
    float2 r; asm("mov.b64 {%0,%1},%2;" : "=f"(r.x), "=f"(r.y) : "l"(a)); return r;
}
__device__ __forceinline__ float gelu_f(float yv) {
    float c_ = fmaf(0.044715f, yv * yv, 1.f);
    float q_ = -1.5957691216f * yv * c_;
    return __fdividef(yv, 1.f + __expf(q_));            // yv * sigmoid(2*0.79788*yv*c)
}
__device__ __forceinline__ uint32_t to_tf32(float f) {
    uint32_t u; asm("cvt.rna.tf32.f32 %0, %1;" : "=r"(u) : "f"(f)); return u;
}
__device__ __forceinline__ void mma_tf32(float* d, const uint32_t* a, const uint32_t* b) {
    asm volatile(
        "mma.sync.aligned.m16n8k8.row.col.f32.tf32.tf32.f32 "
        "{%0,%1,%2,%3}, {%4,%5,%6,%7}, {%8,%9}, {%0,%1,%2,%3};"
        : "+f"(d[0]), "+f"(d[1]), "+f"(d[2]), "+f"(d[3])
        : "r"(a[0]), "r"(a[1]), "r"(a[2]), "r"(a[3]), "r"(b[0]), "r"(b[1]));
}

// ---------------------------------------------------------------------------
// Setup 1: SSM params + w^64; zero pooled.
// ---------------------------------------------------------------------------
__global__ void setup_kernel(const float* __restrict__ log_dt,
                             const float* __restrict__ log_A_real,
                             const float* __restrict__ A_imag,
                             const float* __restrict__ C_re,
                             const float* __restrict__ C_im) {
    int i = blockIdx.x * blockDim.x + threadIdx.x;
    if (i < H_ * N_) {
        int h = i >> 5;
        float dt = expf(log_dt[h]);
        float ar = -expf(log_A_real[i]);
        float ai = A_imag[i];
        float er = expf(dt * ar);
        float si, co;
        sincosf(dt * ai, &si, &co);
        float wr = er * co, wi = er * si;       // w = exp(dt*A)
        float inv = 1.f / (ar * ar + ai * ai);
        float dr = wr - 1.f;
        float qr = (dr * ar + wi * ai) * inv;   // (w-1)/A
        float qi = (wi * ar - dr * ai) * inv;
        float cr = C_re[i], ci = C_im[i];
        float kr = 2.f * (cr * qr - ci * qi);   // k = 2*C*(w-1)/A
        float ki = 2.f * (cr * qi + ci * qr);
        g_wk[i] = make_float4(wr, wi, kr, ki);
        float tr = wr, ti = wi;                  // w^64 by 6 squarings
        #pragma unroll
        for (int s = 0; s < 6; ++s) {
            float nr = tr * tr - ti * ti;
            ti = 2.f * tr * ti;
            tr = nr;
        }
        g_wT[i] = make_float2(tr, ti);
    }
    if (i < B_ * H_) g_pooled[i] = 0.f;
}

// ---------------------------------------------------------------------------
// Setup 2: per-head matrices (plain floats, row-major [k][r]).
// ---------------------------------------------------------------------------
__global__ void setup2_kernel(const float* __restrict__ D) {
    __shared__ float wr[TC + 1][32], wim[TC + 1][32];
    __shared__ float skr[32], ski[32], kap[TC];
    int h = blockIdx.x, t = threadIdx.x;
    if (t < 32) {
        float4 wk = g_wk[h * N_ + t];
        skr[t] = wk.z; ski[t] = wk.w;
        float cr = 1.f, ci = 0.f;
        for (int d = 0; d <= TC; ++d) {
            wr[d][t] = cr; wim[d][t] = ci;
            float nr = cr * wk.x - ci * wk.y;
            ci = cr * wk.y + ci * wk.x;
            cr = nr;
        }
    }
    __syncthreads();
    {   // kappa[t] = Re(sum_n k_n w_n^t)
        float s = 0.f;
        #pragma unroll
        for (int n = 0; n < 32; ++n)
            s += skr[n] * wr[t][n] - ski[n] * wim[t][n];
        kap[t] = s;
    }
    __syncthreads();
    float Dh = D[h];
    for (int idx = t; idx < TC * TC; idx += 64) {
        int k = idx >> 6, r = idx & 63, n = r & 31;
        g_A1f[((size_t)h * TC + k) * TC + r] = (r < 32) ? wr[63 - k][n] : wim[63 - k][n];
    }
    for (int idx = t; idx < 2 * TC * TC; idx += 64) {
        int k = idx >> 6, tt = idx & 63;
        float v;
        if (k < 64)      v = (tt > k) ? kap[tt - k] : (tt == k ? kap[0] + Dh : 0.f);
        else if (k < 96) { int n = k - 64; v = skr[n] * wr[tt + 1][n] - ski[n] * wim[tt + 1][n]; }
        else             { int n = k - 96; v = -(skr[n] * wim[tt + 1][n] + ski[n] * wr[tt + 1][n]); }
        g_A2f[((size_t)h * 2 * TC + k) * TC + tt] = v;
    }
}

// ---------------------------------------------------------------------------
// Fused SSM (unchanged, proven): block = (h, b), 196 KB dyn smem.
// ---------------------------------------------------------------------------
#define SB_STRIDE 130      /* ull stride, even -> 16B-aligned rows */
#define SFC_STRIDE 68
#define SMEM_BYTES 200704  /* 32768 (A) + 133120 (sB) + 34816 (sFC) */

#define GBODY {                                                              \
    ulonglong2 a = *reinterpret_cast<const ulonglong2*>(ap);                 \
    ulonglong2 u01 = *reinterpret_cast<const ulonglong2*>(up);               \
    ulonglong2 u23 = *reinterpret_cast<const ulonglong2*>(up + 2);           \
    ulonglong2 u45 = *reinterpret_cast<const ulonglong2*>(up + 4);           \
    ulonglong2 u67 = *reinterpret_cast<const ulonglong2*>(up + 6);           \
    acc[0][0]=fma2(a.x,u01.x,acc[0][0]); acc[1][0]=fma2(a.y,u01.x,acc[1][0]);\
    acc[0][1]=fma2(a.x,u01.y,acc[0][1]); acc[1][1]=fma2(a.y,u01.y,acc[1][1]);\
    acc[0][2]=fma2(a.x,u23.x,acc[0][2]); acc[1][2]=fma2(a.y,u23.x,acc[1][2]);\
    acc[0][3]=fma2(a.x,u23.y,acc[0][3]); acc[1][3]=fma2(a.y,u23.y,acc[1][3]);\
    acc[0][4]=fma2(a.x,u45.x,acc[0][4]); acc[1][4]=fma2(a.y,u45.x,acc[1][4]);\
    acc[0][5]=fma2(a.x,u45.y,acc[0][5]); acc[1][5]=fma2(a.y,u45.y,acc[1][5]);\
    acc[0][6]=fma2(a.x,u67.x,acc[0][6]); acc[1][6]=fma2(a.y,u67.x,acc[1][6]);\
    acc[0][7]=fma2(a.x,u67.y,acc[0][7]); acc[1][7]=fma2(a.y,u67.y,acc[1][7]);\
    ap += TC; up += SB_STRIDE;                                               \
}

__global__ void __launch_bounds__(256) ssm_kernel(const float* __restrict__ x,
                                                  const float* __restrict__ enc_w,
                                                  const float* __restrict__ enc_b) {
    extern __shared__ char smem[];
    float* sA  = reinterpret_cast<float*>(smem);                 // [k][64 r/t]
    ull*   sB  = reinterpret_cast<ull*>(smem + 32768);           // [k][128 col] dup'd
    float* sFC = reinterpret_cast<float*>(smem + 165888);        // [col][64 r]
    int tid = threadIdx.x;
    int tx = tid & 15, ty = tid >> 4;    // rows 4tx..4tx+3, cols 8ty..8ty+7
    int h = blockIdx.x >> 3, b = blockIdx.x & 7;

    float e0 = enc_w[h], e1 = enc_w[H_ + h], eb = enc_b[h];
    const float2* xb = reinterpret_cast<const float2*>(x) + (size_t)b * L_;
    #pragma unroll
    for (int m = tid; m < 8192; m += 256) {
        float2 xv = xb[m];
        float u = fmaf(e1, xv.y, fmaf(e0, xv.x, eb));
        sB[(size_t)(m & 63) * SB_STRIDE + (m >> 6)] = pack2(u, u);
    }
    {
        const float4* A1p = reinterpret_cast<const float4*>(g_A1f + (size_t)h * TC * TC);
        float4* sA4 = reinterpret_cast<float4*>(sA);
        #pragma unroll
        for (int m = tid; m < 1024; m += 256) sA4[m] = A1p[m];
    }
    __syncthreads();

    ull acc[2][8];
    #pragma unroll
    for (int c = 0; c < 8; ++c) { acc[0][c] = 0ull; acc[1][c] = 0ull; }
    {
        const float* ap = sA + 4 * tx;
        const ull* up = sB + 8 * ty;
        #pragma unroll 4
        for (int k = 0; k < TC; ++k) GBODY
    }
    #pragma unroll
    for (int c = 0; c < 8; ++c) {
        float2 r0 = unpack2(acc[0][c]), r1 = unpack2(acc[1][c]);
        *reinterpret_cast<float4*>(sFC + (8 * ty + c) * SFC_STRIDE + 4 * tx) =
            make_float4(r0.x, r0.y, r1.x, r1.y);
    }
    __syncthreads();

    {
        const float4* A2p = reinterpret_cast<const float4*>(g_A2f + (size_t)h * 2 * TC * TC);
        float4* sA4 = reinterpret_cast<float4*>(sA);
        #pragma unroll
        for (int m = tid; m < 2048; m += 256) sA4[m] = A2p[m];
    }
    if (tid < 32) {          // chain: c(j) = w^64 c(j-1) + f(j-1), overwrite F->C
        float2 wT = g_wT[h * N_ + tid];
        float wTx = wT.x, wTy = wT.y;
        float cr = 0.f, ci = 0.f;
        float* fr0 = sFC + tid;
        float* fi0 = sFC + 32 + tid;
        for (int j = 0; j < J_; j += 4) {
            float fr[4], fi[4];
            #pragma unroll
            for (int q = 0; q < 4; ++q) {
                fr[q] = fr0[(j + q) * SFC_STRIDE];
                fi[q] = fi0[(j + q) * SFC_STRIDE];
            }
            #pragma unroll
            for (int q = 0; q < 4; ++q) {
                fr0[(j + q) * SFC_STRIDE] = cr;
                fi0[(j + q) * SFC_STRIDE] = ci;
                float nr = fmaf(wTx, cr, fmaf(-wTy, ci, fr[q]));
                ci = fmaf(wTy, cr, fmaf(wTx, ci, fi[q]));
                cr = nr;
            }
        }
    }
    __syncthreads();

    #pragma unroll
    for (int m = tid; m < 8192; m += 256) {
        float v = sFC[(m >> 6) * SFC_STRIDE + (m & 63)];
        sB[(size_t)(64 + (m & 63)) * SB_STRIDE + (m >> 6)] = pack2(v, v);
    }
    __syncthreads();

    #pragma unroll
    for (int c = 0; c < 8; ++c) { acc[0][c] = 0ull; acc[1][c] = 0ull; }
    {
        const float* ap = sA + 4 * tx;
        const ull* up = sB + 8 * ty;
        #pragma unroll 4
        for (int k = 0; k < 2 * TC; ++k) GBODY
    }
    float* yb = g_y + ((size_t)b * H_ + h) * L_;
    #pragma unroll
    for (int c = 0; c < 8; ++c) {
        int col = 8 * ty + c;
        float2 r0 = unpack2(acc[0][c]), r1 = unpack2(acc[1][c]);
        float4 o = make_float4(gelu_f(r0.x), gelu_f(r0.y), gelu_f(r1.x), gelu_f(r1.y));
        *reinterpret_cast<float4*>(yb + (size_t)col * TC + 4 * tx) = o;
    }
}

// ---------------------------------------------------------------------------
// GLU via mma.sync tf32 (m16n8k8): Z[256,128] = out_w[256,128] @ Y[128,128],
// GLU + pool epilogue through smem. Block = (b, 128-token tile); 512 CTAs.
// sW: tf32 [256][132-pad] (A row-major; conflict-free frag LDS).
// sY: tf32 [128][136-pad] (B; conflict-free frag LDS).
// Z reuses the sW region (float, stride 132) after a sync.
// ---------------------------------------------------------------------------
#define SW_S 132
#define SY_S 136
#define SY_OFF 135168                     /* 256*132*4 */
#define GLU_SMEM 204800                   /* + 128*136*4 */

__global__ void __launch_bounds__(256) glu_mma_kernel(const float* __restrict__ out_w,
                                                      const float* __restrict__ out_b) {
    extern __shared__ char smem[];
    uint32_t* sW = reinterpret_cast<uint32_t*>(smem);
    uint32_t* sY = reinterpret_cast<uint32_t*>(smem + SY_OFF);
    float*    sZ = reinterpret_cast<float*>(smem);
    int tid = threadIdx.x;
    int wid = tid >> 5, lane = tid & 31;
    int qr = lane >> 2, qc = lane & 3;
    int bidx = blockIdx.x;
    int b = bidx >> 6, l0 = (bidx & 63) << 7;

    // ---- stage W as tf32: sW[g][k] = out_w[g*128+k] ----
    #pragma unroll
    for (int m = tid; m < 8192; m += 256) {
        int row = m >> 5, c4 = (m & 31) << 2;
        float4 v = *reinterpret_cast<const float4*>(out_w + (size_t)row * H_ + c4);
        uint4 u = make_uint4(to_tf32(v.x), to_tf32(v.y), to_tf32(v.z), to_tf32(v.w));
        *reinterpret_cast<uint4*>(sW + row * SW_S + c4) = u;
    }
    // ---- stage Y tile as tf32: sY[h][t] = y[b][h][l0+t] ----
    const float* yb = g_y + (size_t)b * H_ * L_ + l0;
    #pragma unroll
    for (int m = tid; m < 4096; m += 256) {
        int hh = m >> 5, t4 = (m & 31) << 2;
        float4 v = *reinterpret_cast<const float4*>(yb + (size_t)hh * L_ + t4);
        uint4 u = make_uint4(to_tf32(v.x), to_tf32(v.y), to_tf32(v.z), to_tf32(v.w));
        *reinterpret_cast<uint4*>(sY + hh * SY_S + t4) = u;
    }
    __syncthreads();

    // ---- mainloop: warp owns g-rows [32w,32w+32), all 128 tokens ----
    int gm = wid << 5;
    float d[2][16][4];
    #pragma unroll
    for (int mt = 0; mt < 2; ++mt)
        #pragma unroll
        for (int j = 0; j < 16; ++j)
            #pragma unroll
            for (int q = 0; q < 4; ++q) d[mt][j][q] = 0.f;

    const uint32_t* wA = sW + (gm + qr) * SW_S + qc;
    #pragma unroll 2
    for (int s = 0; s < 16; ++s) {
        int kk = s << 3;
        uint32_t a[2][4];
        #pragma unroll
        for (int mt = 0; mt < 2; ++mt) {
            const uint32_t* wp = wA + mt * 16 * SW_S + kk;
            a[mt][0] = wp[0];
            a[mt][1] = wp[8 * SW_S];
            a[mt][2] = wp[4];
            a[mt][3] = wp[8 * SW_S + 4];
        }
        const uint32_t* y0 = sY + (kk + qc) * SY_S + qr;
        const uint32_t* y1 = y0 + 4 * SY_S;
        uint32_t bb[16][2];
        #pragma unroll
        for (int j = 0; j < 16; ++j) { bb[j][0] = y0[j << 3]; bb[j][1] = y1[j << 3]; }
        #pragma unroll
        for (int mt = 0; mt < 2; ++mt)
            #pragma unroll
            for (int j = 0; j < 16; ++j)
                mma_tf32(d[mt][j], a[mt], bb[j]);
    }
    __syncthreads();     // all frag reads of sW done before Z overwrite

    // ---- write Z into sW region ----
    #pragma unroll
    for (int mt = 0; mt < 2; ++mt) {
        #pragma unroll
        for (int j = 0; j < 16; ++j) {
            int r = gm + (mt << 4) + qr;
            int nn = (j << 3) + (qc << 1);
            *reinterpret_cast<float2*>(sZ + r * SW_S + nn) =
                make_float2(d[mt][j][0], d[mt][j][1]);
            *reinterpret_cast<float2*>(sZ + (r + 8) * SW_S + nn) =
                make_float2(d[mt][j][2], d[mt][j][3]);
        }
    }
    __syncthreads();

    // ---- GLU + pool: thread -> (g = tid&127, n half = tid>>7) ----
    {
        int g = tid & 127, half = tid >> 7;
        float bA = out_b[g], bG = out_b[128 + g];
        const float* za = sZ + g * SW_S + (half << 6);
        const float* zg = sZ + (128 + g) * SW_S + (half << 6);
        float s = 0.f;
        #pragma unroll 8
        for (int n = 0; n < 64; ++n) {
            float av = za[n] + bA;
            float qv = zg[n] + bG;
            s += av * __fdividef(1.f, 1.f + __expf(-qv));
        }
        atomicAdd(&g_pooled[b * H_ + g], s);
    }
}

// ---------------------------------------------------------------------------
// Decode: out[b] = (pooled_sum[b,:]/L) . dec_w + dec_b
// ---------------------------------------------------------------------------
__global__ void decode_kernel(const float* __restrict__ dec_w,
                              const float* __restrict__ dec_b,
                              float* __restrict__ out) {
    int wid = threadIdx.x >> 5, lane = threadIdx.x & 31;
    int b = wid;
    float p = 0.f;
    #pragma unroll
    for (int i = 0; i < 4; i++) {
        int h = lane + 32 * i;
        p += g_pooled[b * H_ + h] * dec_w[h];
    }
    p += __shfl_xor_sync(0xffffffffu, p, 16);
    p += __shfl_xor_sync(0xffffffffu, p, 8);
    p += __shfl_xor_sync(0xffffffffu, p, 4);
    p += __shfl_xor_sync(0xffffffffu, p, 2);
    p += __shfl_xor_sync(0xffffffffu, p, 1);
    if (lane == 0) out[b] = p * (1.f / (float)L_) + dec_b[0];
}

// ---------------------------------------------------------------------------
extern "C" void kernel_launch(void* const* d_in, const int* in_sizes, int n_in,
                              void* d_out, int out_size) {
    const float* x      = (const float*)d_in[0];
    const float* enc_w  = (const float*)d_in[1];
    const float* enc_b  = (const float*)d_in[2];
    const float* log_dt = (const float*)d_in[3];
    const float* log_A  = (const float*)d_in[4];
    const float* A_im   = (const float*)d_in[5];
    const float* C_re   = (const float*)d_in[6];
    const float* C_im   = (const float*)d_in[7];
    const float* D      = (const float*)d_in[8];
    const float* out_w  = (const float*)d_in[9];
    const float* out_b  = (const float*)d_in[10];
    const float* dec_w  = (const float*)d_in[11];
    const float* dec_b  = (const float*)d_in[12];
    float* out = (float*)d_out;

    cudaFuncSetAttribute(ssm_kernel, cudaFuncAttributeMaxDynamicSharedMemorySize,
                         SMEM_BYTES);
    cudaFuncSetAttribute(glu_mma_kernel, cudaFuncAttributeMaxDynamicSharedMemorySize,
                         GLU_SMEM);

    setup_kernel<<<16, 256>>>(log_dt, log_A, A_im, C_re, C_im);
    setup2_kernel<<<128, 64>>>(D);
    ssm_kernel<<<1024, 256, SMEM_BYTES>>>(x, enc_w, enc_b);
    glu_mma_kernel<<<512, 256, GLU_SMEM>>>(out_w, out_b);
    decode_kernel<<<1, 256>>>(dec_w, dec_b, out);
}

// round 14
// speedup vs baseline: 2.5214x; 1.3365x over previous
#include <cuda_runtime.h>
#include <cstdint>

#define B_ 8
#define L_ 8192
#define H_ 128
#define N_ 32
#define G_ 256   /* 2H */
#define TC 64    /* chunk length */
#define J_ 128   /* chunks per sequence */

typedef unsigned long long ull;

// Scratch (static __device__ arrays: no allocation anywhere)
__device__ float4 g_wk[H_ * N_];                        // {w_re, w_im, k_re, k_im}
__device__ float2 g_wT[H_ * N_];                        // w^64
__device__ __align__(16) float g_A1t[(size_t)H_ * TC * TC];      // finals matrix [h][r][k]
__device__ __align__(16) float g_A2t[(size_t)H_ * TC * 2 * TC];  // [Tri+D | V]   [h][t][k]
__device__ float  g_y[(size_t)B_ * H_ * L_];            // post-GELU activations (B,H,L)
__device__ float  g_pooled[B_ * H_];

__device__ __forceinline__ float gelu_f(float yv) {
    float c_ = fmaf(0.044715f, yv * yv, 1.f);
    float q_ = -1.5957691216f * yv * c_;
    return __fdividef(yv, 1.f + __expf(q_));            // yv * sigmoid(2*0.79788*yv*c)
}
__device__ __forceinline__ uint32_t to_tf32(float f) {
    uint32_t u; asm("cvt.rna.tf32.f32 %0, %1;" : "=r"(u) : "f"(f)); return u;
}
__device__ __forceinline__ void mma_tf32(float* d, const uint32_t* a, const uint32_t* b) {
    asm volatile(
        "mma.sync.aligned.m16n8k8.row.col.f32.tf32.tf32.f32 "
        "{%0,%1,%2,%3}, {%4,%5,%6,%7}, {%8,%9}, {%0,%1,%2,%3};"
        : "+f"(d[0]), "+f"(d[1]), "+f"(d[2]), "+f"(d[3])
        : "r"(a[0]), "r"(a[1]), "r"(a[2]), "r"(a[3]), "r"(b[0]), "r"(b[1]));
}

// ---------------------------------------------------------------------------
// Setup 1: SSM params + w^64; zero pooled.
// ---------------------------------------------------------------------------
__global__ void setup_kernel(const float* __restrict__ log_dt,
                             const float* __restrict__ log_A_real,
                             const float* __restrict__ A_imag,
                             const float* __restrict__ C_re,
                             const float* __restrict__ C_im) {
    int i = blockIdx.x * blockDim.x + threadIdx.x;
    if (i < H_ * N_) {
        int h = i >> 5;
        float dt = expf(log_dt[h]);
        float ar = -expf(log_A_real[i]);
        float ai = A_imag[i];
        float er = expf(dt * ar);
        float si, co;
        sincosf(dt * ai, &si, &co);
        float wr = er * co, wi = er * si;       // w = exp(dt*A)
        float inv = 1.f / (ar * ar + ai * ai);
        float dr = wr - 1.f;
        float qr = (dr * ar + wi * ai) * inv;   // (w-1)/A
        float qi = (wi * ar - dr * ai) * inv;
        float cr = C_re[i], ci = C_im[i];
        float kr = 2.f * (cr * qr - ci * qi);   // k = 2*C*(w-1)/A
        float ki = 2.f * (cr * qi + ci * qr);
        g_wk[i] = make_float4(wr, wi, kr, ki);
        float tr = wr, ti = wi;                  // w^64 by 6 squarings
        #pragma unroll
        for (int s = 0; s < 6; ++s) {
            float nr = tr * tr - ti * ti;
            ti = 2.f * tr * ti;
            tr = nr;
        }
        g_wT[i] = make_float2(tr, ti);
    }
    if (i < B_ * H_) g_pooled[i] = 0.f;
}

// ---------------------------------------------------------------------------
// Setup 2: per-head matrices, TRANSPOSED to [row][k] (row-major A for mma).
// A1t[r][k]: r<32: Re(w_r^{63-k}); r>=32: Im(w_{r-32}^{63-k}).
// A2t[t][k]: k<64: kappa[t-k] (t>k), diag kap0+D; k=64+n: Re(k_n w_n^{t+1});
//            k=96+n: -Im(k_n w_n^{t+1}).
// ---------------------------------------------------------------------------
__global__ void setup2_kernel(const float* __restrict__ D) {
    __shared__ float wr[TC + 1][32], wim[TC + 1][32];
    __shared__ float skr[32], ski[32], kap[TC];
    int h = blockIdx.x, t = threadIdx.x;
    if (t < 32) {
        float4 wk = g_wk[h * N_ + t];
        skr[t] = wk.z; ski[t] = wk.w;
        float cr = 1.f, ci = 0.f;
        for (int d = 0; d <= TC; ++d) {
            wr[d][t] = cr; wim[d][t] = ci;
            float nr = cr * wk.x - ci * wk.y;
            ci = cr * wk.y + ci * wk.x;
            cr = nr;
        }
    }
    __syncthreads();
    {   // kappa[t] = Re(sum_n k_n w_n^t)
        float s = 0.f;
        #pragma unroll
        for (int n = 0; n < 32; ++n)
            s += skr[n] * wr[t][n] - ski[n] * wim[t][n];
        kap[t] = s;
    }
    __syncthreads();
    float Dh = D[h];
    for (int idx = t; idx < TC * TC; idx += 64) {
        int r = idx >> 6, k = idx & 63;
        g_A1t[(size_t)h * 4096 + idx] = (r < 32) ? wr[63 - k][r] : wim[63 - k][r - 32];
    }
    for (int idx = t; idx < TC * 2 * TC; idx += 64) {
        int tt = idx >> 7, k = idx & 127;
        float v;
        if (k < 64)      v = (tt > k) ? kap[tt - k] : (tt == k ? kap[0] + Dh : 0.f);
        else if (k < 96) { int n = k - 64; v = skr[n] * wr[tt + 1][n] - ski[n] * wim[tt + 1][n]; }
        else             { int n = k - 96; v = -(skr[n] * wim[tt + 1][n] + ski[n] * wr[tt + 1][n]); }
        g_A2t[(size_t)h * 8192 + idx] = v;
    }
}

// ---------------------------------------------------------------------------
// Fused SSM via mma.sync tf32. Block = (h, b), 256 thr, 152 KB dyn smem.
//   GEMM1: F[64 r][128 col] = A1t[64][64] @ U[64][128]
//   chain (warp 0, fp32, in smem) while A2 loads
//   GEMM2: Y[64 t][128 col] = A2t[64][128] @ [U;C][128][128]; GELU; STG.
// Warp w: rows (w&3)*16..+15, cols (w>>2)*64..+63 (8 n-frags).
// ---------------------------------------------------------------------------
#define SA1_S 68
#define SA2_S 132
#define SBT_S 136
#define OFF_A2 17408
#define OFF_B  51200
#define OFF_FC 120832
#define SSM_SMEM 155648

__global__ void __launch_bounds__(256) ssm_mma_kernel(const float* __restrict__ x,
                                                      const float* __restrict__ enc_w,
                                                      const float* __restrict__ enc_b) {
    extern __shared__ char smem[];
    uint32_t* sA1 = reinterpret_cast<uint32_t*>(smem);           // [r][68]
    uint32_t* sA2 = reinterpret_cast<uint32_t*>(smem + OFF_A2);  // [t][132]
    uint32_t* sB  = reinterpret_cast<uint32_t*>(smem + OFF_B);   // [k][136]
    float*    sFC = reinterpret_cast<float*>(smem + OFF_FC);     // [col][68]
    int tid = threadIdx.x;
    int wid = tid >> 5, lane = tid & 31;
    int qr = lane >> 2, qc = lane & 3;
    int gm = (wid & 3) << 4, nh = (wid >> 2) << 6;
    int h = blockIdx.x >> 3, b = blockIdx.x & 7;

    // ---- encoder fill: U rows 0..63 of sB (tf32) ----
    float e0 = enc_w[h], e1 = enc_w[H_ + h], eb = enc_b[h];
    const float2* xb = reinterpret_cast<const float2*>(x) + (size_t)b * L_;
    #pragma unroll
    for (int m = tid; m < 8192; m += 256) {
        float2 xv = xb[m];
        float u = fmaf(e1, xv.y, fmaf(e0, xv.x, eb));
        sB[(m & 63) * SBT_S + (m >> 6)] = to_tf32(u);
    }
    // ---- load A1 ----
    {
        const float* A1p = g_A1t + (size_t)h * 4096;
        #pragma unroll
        for (int m = tid; m < 4096; m += 256)
            sA1[(m >> 6) * SA1_S + (m & 63)] = to_tf32(A1p[m]);
    }
    __syncthreads();

    // ---- GEMM1 ----
    float d[8][4];
    #pragma unroll
    for (int j = 0; j < 8; ++j)
        #pragma unroll
        for (int q = 0; q < 4; ++q) d[j][q] = 0.f;
    {
        const uint32_t* wA = sA1 + (gm + qr) * SA1_S + qc;
        #pragma unroll
        for (int s = 0; s < 8; ++s) {
            int kk = s << 3;
            uint32_t a[4];
            const uint32_t* wp = wA + kk;
            a[0] = wp[0]; a[1] = wp[8 * SA1_S]; a[2] = wp[4]; a[3] = wp[8 * SA1_S + 4];
            const uint32_t* y0 = sB + (kk + qc) * SBT_S + nh + qr;
            #pragma unroll
            for (int j = 0; j < 8; ++j) {
                uint32_t bb[2] = { y0[j << 3], y0[4 * SBT_S + (j << 3)] };
                mma_tf32(d[j], a, bb);
            }
        }
    }
    // F -> sFC[col][r]
    #pragma unroll
    for (int j = 0; j < 8; ++j) {
        int nn = nh + (j << 3) + (qc << 1);
        sFC[nn * 68 + gm + qr]           = d[j][0];
        sFC[(nn + 1) * 68 + gm + qr]     = d[j][1];
        sFC[nn * 68 + gm + qr + 8]       = d[j][2];
        sFC[(nn + 1) * 68 + gm + qr + 8] = d[j][3];
    }
    __syncthreads();

    // ---- load A2 while warp 0 runs the carry chain (fp32, in sFC) ----
    {
        const float* A2p = g_A2t + (size_t)h * 8192;
        #pragma unroll
        for (int m = tid; m < 8192; m += 256)
            sA2[(m >> 7) * SA2_S + (m & 127)] = to_tf32(A2p[m]);
    }
    if (tid < 32) {          // c(j) = w^64 c(j-1) + f(j-1), overwrite F->C
        float2 wT = g_wT[h * N_ + tid];
        float wTx = wT.x, wTy = wT.y;
        float cr = 0.f, ci = 0.f;
        float* fr0 = sFC + tid;
        float* fi0 = sFC + 32 + tid;
        for (int j = 0; j < J_; j += 4) {
            float fr[4], fi[4];
            #pragma unroll
            for (int q = 0; q < 4; ++q) {
                fr[q] = fr0[(j + q) * 68];
                fi[q] = fi0[(j + q) * 68];
            }
            #pragma unroll
            for (int q = 0; q < 4; ++q) {
                fr0[(j + q) * 68] = cr;
                fi0[(j + q) * 68] = ci;
                float nr = fmaf(wTx, cr, fmaf(-wTy, ci, fr[q]));
                ci = fmaf(wTy, cr, fmaf(wTx, ci, fi[q]));
                cr = nr;
            }
        }
    }
    __syncthreads();

    // ---- dup carries into sB rows 64..127 (tf32) ----
    #pragma unroll
    for (int m = tid; m < 8192; m += 256)
        sB[(64 + (m & 63)) * SBT_S + (m >> 6)] = to_tf32(sFC[(m >> 6) * 68 + (m & 63)]);
    __syncthreads();

    // ---- GEMM2 ----
    #pragma unroll
    for (int j = 0; j < 8; ++j)
        #pragma unroll
        for (int q = 0; q < 4; ++q) d[j][q] = 0.f;
    {
        const uint32_t* wA = sA2 + (gm + qr) * SA2_S + qc;
        #pragma unroll 2
        for (int s = 0; s < 16; ++s) {
            int kk = s << 3;
            uint32_t a[4];
            const uint32_t* wp = wA + kk;
            a[0] = wp[0]; a[1] = wp[8 * SA2_S]; a[2] = wp[4]; a[3] = wp[8 * SA2_S + 4];
            const uint32_t* y0 = sB + (kk + qc) * SBT_S + nh + qr;
            #pragma unroll
            for (int j = 0; j < 8; ++j) {
                uint32_t bb[2] = { y0[j << 3], y0[4 * SBT_S + (j << 3)] };
                mma_tf32(d[j], a, bb);
            }
        }
    }
    __syncthreads();        // carry-dup reads of sFC complete before sZ overwrite

    // ---- epilogue: GELU -> sZ[col][t] (reuse sFC), then coalesced STG ----
    float* sZ = sFC;
    #pragma unroll
    for (int j = 0; j < 8; ++j) {
        int nn = nh + (j << 3) + (qc << 1);
        sZ[nn * 68 + gm + qr]           = gelu_f(d[j][0]);
        sZ[(nn + 1) * 68 + gm + qr]     = gelu_f(d[j][1]);
        sZ[nn * 68 + gm + qr + 8]       = gelu_f(d[j][2]);
        sZ[(nn + 1) * 68 + gm + qr + 8] = gelu_f(d[j][3]);
    }
    __syncthreads();
    float* yb = g_y + ((size_t)b * H_ + h) * L_;
    #pragma unroll
    for (int idx = tid; idx < 2048; idx += 256) {
        int col = idx >> 4, t4 = (idx & 15) << 2;
        float4 v = *reinterpret_cast<const float4*>(sZ + col * 68 + t4);
        *reinterpret_cast<float4*>(yb + col * TC + t4) = v;
    }
}

// ---------------------------------------------------------------------------
// GLU via mma.sync tf32 (proven R12 kernel, unchanged).
// ---------------------------------------------------------------------------
#define SW_S 132
#define SY_S 136
#define SY_OFF 135168                     /* 256*132*4 */
#define GLU_SMEM 204800                   /* + 128*136*4 */

__global__ void __launch_bounds__(256) glu_mma_kernel(const float* __restrict__ out_w,
                                                      const float* __restrict__ out_b) {
    extern __shared__ char smem[];
    uint32_t* sW = reinterpret_cast<uint32_t*>(smem);
    uint32_t* sY = reinterpret_cast<uint32_t*>(smem + SY_OFF);
    float*    sZ = reinterpret_cast<float*>(smem);
    int tid = threadIdx.x;
    int wid = tid >> 5, lane = tid & 31;
    int qr = lane >> 2, qc = lane & 3;
    int bidx = blockIdx.x;
    int b = bidx >> 6, l0 = (bidx & 63) << 7;

    #pragma unroll
    for (int m = tid; m < 8192; m += 256) {
        int row = m >> 5, c4 = (m & 31) << 2;
        float4 v = *reinterpret_cast<const float4*>(out_w + (size_t)row * H_ + c4);
        uint4 u = make_uint4(to_tf32(v.x), to_tf32(v.y), to_tf32(v.z), to_tf32(v.w));
        *reinterpret_cast<uint4*>(sW + row * SW_S + c4) = u;
    }
    const float* yb = g_y + (size_t)b * H_ * L_ + l0;
    #pragma unroll
    for (int m = tid; m < 4096; m += 256) {
        int hh = m >> 5, t4 = (m & 31) << 2;
        float4 v = *reinterpret_cast<const float4*>(yb + (size_t)hh * L_ + t4);
        uint4 u = make_uint4(to_tf32(v.x), to_tf32(v.y), to_tf32(v.z), to_tf32(v.w));
        *reinterpret_cast<uint4*>(sY + hh * SY_S + t4) = u;
    }
    __syncthreads();

    int gm = wid << 5;
    float d[2][16][4];
    #pragma unroll
    for (int mt = 0; mt < 2; ++mt)
        #pragma unroll
        for (int j = 0; j < 16; ++j)
            #pragma unroll
            for (int q = 0; q < 4; ++q) d[mt][j][q] = 0.f;

    const uint32_t* wA = sW + (gm + qr) * SW_S + qc;
    #pragma unroll 2
    for (int s = 0; s < 16; ++s) {
        int kk = s << 3;
        uint32_t a[2][4];
        #pragma unroll
        for (int mt = 0; mt < 2; ++mt) {
            const uint32_t* wp = wA + mt * 16 * SW_S + kk;
            a[mt][0] = wp[0];
            a[mt][1] = wp[8 * SW_S];
            a[mt][2] = wp[4];
            a[mt][3] = wp[8 * SW_S + 4];
        }
        const uint32_t* y0 = sY + (kk + qc) * SY_S + qr;
        const uint32_t* y1 = y0 + 4 * SY_S;
        uint32_t bb[16][2];
        #pragma unroll
        for (int j = 0; j < 16; ++j) { bb[j][0] = y0[j << 3]; bb[j][1] = y1[j << 3]; }
        #pragma unroll
        for (int mt = 0; mt < 2; ++mt)
            #pragma unroll
            for (int j = 0; j < 16; ++j)
                mma_tf32(d[mt][j], a[mt], bb[j]);
    }
    __syncthreads();

    #pragma unroll
    for (int mt = 0; mt < 2; ++mt) {
        #pragma unroll
        for (int j = 0; j < 16; ++j) {
            int r = gm + (mt << 4) + qr;
            int nn = (j << 3) + (qc << 1);
            *reinterpret_cast<float2*>(sZ + r * SW_S + nn) =
                make_float2(d[mt][j][0], d[mt][j][1]);
            *reinterpret_cast<float2*>(sZ + (r + 8) * SW_S + nn) =
                make_float2(d[mt][j][2], d[mt][j][3]);
        }
    }
    __syncthreads();

    {
        int g = tid & 127, half = tid >> 7;
        float bA = out_b[g], bG = out_b[128 + g];
        const float* za = sZ + g * SW_S + (half << 6);
        const float* zg = sZ + (128 + g) * SW_S + (half << 6);
        float s = 0.f;
        #pragma unroll 8
        for (int n = 0; n < 64; ++n) {
            float av = za[n] + bA;
            float qv = zg[n] + bG;
            s += av * __fdividef(1.f, 1.f + __expf(-qv));
        }
        atomicAdd(&g_pooled[b * H_ + g], s);
    }
}

// ---------------------------------------------------------------------------
// Decode: out[b] = (pooled_sum[b,:]/L) . dec_w + dec_b
// ---------------------------------------------------------------------------
__global__ void decode_kernel(const float* __restrict__ dec_w,
                              const float* __restrict__ dec_b,
                              float* __restrict__ out) {
    int wid = threadIdx.x >> 5, lane = threadIdx.x & 31;
    int b = wid;
    float p = 0.f;
    #pragma unroll
    for (int i = 0; i < 4; i++) {
        int h = lane + 32 * i;
        p += g_pooled[b * H_ + h] * dec_w[h];
    }
    p += __shfl_xor_sync(0xffffffffu, p, 16);
    p += __shfl_xor_sync(0xffffffffu, p, 8);
    p += __shfl_xor_sync(0xffffffffu, p, 4);
    p += __shfl_xor_sync(0xffffffffu, p, 2);
    p += __shfl_xor_sync(0xffffffffu, p, 1);
    if (lane == 0) out[b] = p * (1.f / (float)L_) + dec_b[0];
}

// ---------------------------------------------------------------------------
extern "C" void kernel_launch(void* const* d_in, const int* in_sizes, int n_in,
                              void* d_out, int out_size) {
    const float* x      = (const float*)d_in[0];
    const float* enc_w  = (const float*)d_in[1];
    const float* enc_b  = (const float*)d_in[2];
    const float* log_dt = (const float*)d_in[3];
    const float* log_A  = (const float*)d_in[4];
    const float* A_im   = (const float*)d_in[5];
    const float* C_re   = (const float*)d_in[6];
    const float* C_im   = (const float*)d_in[7];
    const float* D      = (const float*)d_in[8];
    const float* out_w  = (const float*)d_in[9];
    const float* out_b  = (const float*)d_in[10];
    const float* dec_w  = (const float*)d_in[11];
    const float* dec_b  = (const float*)d_in[12];
    float* out = (float*)d_out;

    cudaFuncSetAttribute(ssm_mma_kernel, cudaFuncAttributeMaxDynamicSharedMemorySize,
                         SSM_SMEM);
    cudaFuncSetAttribute(glu_mma_kernel, cudaFuncAttributeMaxDynamicSharedMemorySize,
                         GLU_SMEM);

    setup_kernel<<<16, 256>>>(log_dt, log_A, A_im, C_re, C_im);
    setup2_kernel<<<128, 64>>>(D);
    ssm_mma_kernel<<<1024, 256, SSM_SMEM>>>(x, enc_w, enc_b);
    glu_mma_kernel<<<512, 256, GLU_SMEM>>>(out_w, out_b);
    decode_kernel<<<1, 256>>>(dec_w, dec_b, out);
}

// round 15
// speedup vs baseline: 2.6138x; 1.0366x over previous
#include <cuda_runtime.h>
#include <cstdint>

#define B_ 8
#define L_ 8192
#define H_ 128
#define N_ 32
#define G_ 256   /* 2H */
#define TC 64    /* chunk length */
#define J_ 128   /* chunks per sequence */

typedef unsigned long long ull;

// Scratch (static __device__ arrays: no allocation anywhere)
__device__ float2 g_wT[H_ * N_];                        // w^64
__device__ __align__(16) float g_A1t[(size_t)H_ * TC * TC];      // finals matrix [h][r][k]
__device__ __align__(16) float g_A2t[(size_t)H_ * TC * 2 * TC];  // [Tri+D | V]   [h][t][k]
__device__ float  g_y[(size_t)B_ * H_ * L_];            // post-GELU activations (B,H,L)
__device__ float  g_pooled[B_ * H_];

__device__ __forceinline__ float gelu_f(float yv) {
    float c_ = fmaf(0.044715f, yv * yv, 1.f);
    float q_ = -1.5957691216f * yv * c_;
    return __fdividef(yv, 1.f + __expf(q_));            // yv * sigmoid(2*0.79788*yv*c)
}
__device__ __forceinline__ float sigm(float v) {
    return __fdividef(1.f, 1.f + __expf(-v));
}
__device__ __forceinline__ uint32_t to_tf32(float f) {
    uint32_t u; asm("cvt.rna.tf32.f32 %0, %1;" : "=r"(u) : "f"(f)); return u;
}
__device__ __forceinline__ void mma_tf32(float* d, const uint32_t* a, const uint32_t* b) {
    asm volatile(
        "mma.sync.aligned.m16n8k8.row.col.f32.tf32.tf32.f32 "
        "{%0,%1,%2,%3}, {%4,%5,%6,%7}, {%8,%9}, {%0,%1,%2,%3};"
        : "+f"(d[0]), "+f"(d[1]), "+f"(d[2]), "+f"(d[3])
        : "r"(a[0]), "r"(a[1]), "r"(a[2]), "r"(a[3]), "r"(b[0]), "r"(b[1]));
}

// ---------------------------------------------------------------------------
// Setup (merged): per-head SSM params computed in-block, power table,
// A1t/A2t emission, w^64 (table row 64), pooled zeroing.
// 128 blocks (head) x 64 threads.
// ---------------------------------------------------------------------------
__global__ void setup2_kernel(const float* __restrict__ log_dt,
                              const float* __restrict__ log_A_real,
                              const float* __restrict__ A_imag,
                              const float* __restrict__ C_re,
                              const float* __restrict__ C_im,
                              const float* __restrict__ D) {
    __shared__ float wr[TC + 1][32], wim[TC + 1][32];
    __shared__ float skr[32], ski[32], kap[TC];
    int h = blockIdx.x, t = threadIdx.x;
    if (t < 32) {
        int i = h * N_ + t;
        float dt = expf(log_dt[h]);
        float ar = -expf(log_A_real[i]);
        float ai = A_imag[i];
        float er = expf(dt * ar);
        float si, co;
        sincosf(dt * ai, &si, &co);
        float w_r = er * co, w_i = er * si;     // w = exp(dt*A)
        float inv = 1.f / (ar * ar + ai * ai);
        float dr = w_r - 1.f;
        float qr_ = (dr * ar + w_i * ai) * inv; // (w-1)/A
        float qi_ = (w_i * ar - dr * ai) * inv;
        float cr = C_re[i], ci = C_im[i];
        skr[t] = 2.f * (cr * qr_ - ci * qi_);   // k = 2*C*(w-1)/A
        ski[t] = 2.f * (cr * qi_ + ci * qr_);
        float pr = 1.f, pi = 0.f;
        for (int d = 0; d <= TC; ++d) {
            wr[d][t] = pr; wim[d][t] = pi;
            float nr = pr * w_r - pi * w_i;
            pi = pr * w_i + pi * w_r;
            pr = nr;
        }
        g_wT[i] = make_float2(wr[TC][t], wim[TC][t]);   // w^64 from the table
    }
    if (h < 16) g_pooled[h * 64 + t] = 0.f;
    __syncthreads();
    {   // kappa[t] = Re(sum_n k_n w_n^t)
        float s = 0.f;
        #pragma unroll
        for (int n = 0; n < 32; ++n)
            s += skr[n] * wr[t][n] - ski[n] * wim[t][n];
        kap[t] = s;
    }
    __syncthreads();
    float Dh = D[h];
    for (int idx = t; idx < TC * TC; idx += 64) {
        int r = idx >> 6, k = idx & 63;
        g_A1t[(size_t)h * 4096 + idx] = (r < 32) ? wr[63 - k][r] : wim[63 - k][r - 32];
    }
    for (int idx = t; idx < TC * 2 * TC; idx += 64) {
        int tt = idx >> 7, k = idx & 127;
        float v;
        if (k < 64)      v = (tt > k) ? kap[tt - k] : (tt == k ? kap[0] + Dh : 0.f);
        else if (k < 96) { int n = k - 64; v = skr[n] * wr[tt + 1][n] - ski[n] * wim[tt + 1][n]; }
        else             { int n = k - 96; v = -(skr[n] * wim[tt + 1][n] + ski[n] * wr[tt + 1][n]); }
        g_A2t[(size_t)h * 8192 + idx] = v;
    }
}

// ---------------------------------------------------------------------------
// Fused SSM via mma.sync tf32 (proven R13 kernel, unchanged).
// ---------------------------------------------------------------------------
#define SA1_S 68
#define SA2_S 132
#define SBT_S 136
#define OFF_A2 17408
#define OFF_B  51200
#define OFF_FC 120832
#define SSM_SMEM 155648

__global__ void __launch_bounds__(256) ssm_mma_kernel(const float* __restrict__ x,
                                                      const float* __restrict__ enc_w,
                                                      const float* __restrict__ enc_b) {
    extern __shared__ char smem[];
    uint32_t* sA1 = reinterpret_cast<uint32_t*>(smem);           // [r][68]
    uint32_t* sA2 = reinterpret_cast<uint32_t*>(smem + OFF_A2);  // [t][132]
    uint32_t* sB  = reinterpret_cast<uint32_t*>(smem + OFF_B);   // [k][136]
    float*    sFC = reinterpret_cast<float*>(smem + OFF_FC);     // [col][68]
    int tid = threadIdx.x;
    int wid = tid >> 5, lane = tid & 31;
    int qr = lane >> 2, qc = lane & 3;
    int gm = (wid & 3) << 4, nh = (wid >> 2) << 6;
    int h = blockIdx.x >> 3, b = blockIdx.x & 7;

    float e0 = enc_w[h], e1 = enc_w[H_ + h], eb = enc_b[h];
    const float2* xb = reinterpret_cast<const float2*>(x) + (size_t)b * L_;
    #pragma unroll
    for (int m = tid; m < 8192; m += 256) {
        float2 xv = xb[m];
        float u = fmaf(e1, xv.y, fmaf(e0, xv.x, eb));
        sB[(m & 63) * SBT_S + (m >> 6)] = to_tf32(u);
    }
    {
        const float* A1p = g_A1t + (size_t)h * 4096;
        #pragma unroll
        for (int m = tid; m < 4096; m += 256)
            sA1[(m >> 6) * SA1_S + (m & 63)] = to_tf32(A1p[m]);
    }
    __syncthreads();

    float d[8][4];
    #pragma unroll
    for (int j = 0; j < 8; ++j)
        #pragma unroll
        for (int q = 0; q < 4; ++q) d[j][q] = 0.f;
    {
        const uint32_t* wA = sA1 + (gm + qr) * SA1_S + qc;
        #pragma unroll
        for (int s = 0; s < 8; ++s) {
            int kk = s << 3;
            uint32_t a[4];
            const uint32_t* wp = wA + kk;
            a[0] = wp[0]; a[1] = wp[8 * SA1_S]; a[2] = wp[4]; a[3] = wp[8 * SA1_S + 4];
            const uint32_t* y0 = sB + (kk + qc) * SBT_S + nh + qr;
            #pragma unroll
            for (int j = 0; j < 8; ++j) {
                uint32_t bb[2] = { y0[j << 3], y0[4 * SBT_S + (j << 3)] };
                mma_tf32(d[j], a, bb);
            }
        }
    }
    #pragma unroll
    for (int j = 0; j < 8; ++j) {
        int nn = nh + (j << 3) + (qc << 1);
        sFC[nn * 68 + gm + qr]           = d[j][0];
        sFC[(nn + 1) * 68 + gm + qr]     = d[j][1];
        sFC[nn * 68 + gm + qr + 8]       = d[j][2];
        sFC[(nn + 1) * 68 + gm + qr + 8] = d[j][3];
    }
    __syncthreads();

    {
        const float* A2p = g_A2t + (size_t)h * 8192;
        #pragma unroll
        for (int m = tid; m < 8192; m += 256)
            sA2[(m >> 7) * SA2_S + (m & 127)] = to_tf32(A2p[m]);
    }
    if (tid < 32) {          // c(j) = w^64 c(j-1) + f(j-1), overwrite F->C
        float2 wT = g_wT[h * N_ + tid];
        float wTx = wT.x, wTy = wT.y;
        float cr = 0.f, ci = 0.f;
        float* fr0 = sFC + tid;
        float* fi0 = sFC + 32 + tid;
        for (int j = 0; j < J_; j += 4) {
            float fr[4], fi[4];
            #pragma unroll
            for (int q = 0; q < 4; ++q) {
                fr[q] = fr0[(j + q) * 68];
                fi[q] = fi0[(j + q) * 68];
            }
            #pragma unroll
            for (int q = 0; q < 4; ++q) {
                fr0[(j + q) * 68] = cr;
                fi0[(j + q) * 68] = ci;
                float nr = fmaf(wTx, cr, fmaf(-wTy, ci, fr[q]));
                ci = fmaf(wTy, cr, fmaf(wTx, ci, fi[q]));
                cr = nr;
            }
        }
    }
    __syncthreads();

    #pragma unroll
    for (int m = tid; m < 8192; m += 256)
        sB[(64 + (m & 63)) * SBT_S + (m >> 6)] = to_tf32(sFC[(m >> 6) * 68 + (m & 63)]);
    __syncthreads();

    #pragma unroll
    for (int j = 0; j < 8; ++j)
        #pragma unroll
        for (int q = 0; q < 4; ++q) d[j][q] = 0.f;
    {
        const uint32_t* wA = sA2 + (gm + qr) * SA2_S + qc;
        #pragma unroll 2
        for (int s = 0; s < 16; ++s) {
            int kk = s << 3;
            uint32_t a[4];
            const uint32_t* wp = wA + kk;
            a[0] = wp[0]; a[1] = wp[8 * SA2_S]; a[2] = wp[4]; a[3] = wp[8 * SA2_S + 4];
            const uint32_t* y0 = sB + (kk + qc) * SBT_S + nh + qr;
            #pragma unroll
            for (int j = 0; j < 8; ++j) {
                uint32_t bb[2] = { y0[j << 3], y0[4 * SBT_S + (j << 3)] };
                mma_tf32(d[j], a, bb);
            }
        }
    }
    __syncthreads();

    float* sZ = sFC;
    #pragma unroll
    for (int j = 0; j < 8; ++j) {
        int nn = nh + (j << 3) + (qc << 1);
        sZ[nn * 68 + gm + qr]           = gelu_f(d[j][0]);
        sZ[(nn + 1) * 68 + gm + qr]     = gelu_f(d[j][1]);
        sZ[nn * 68 + gm + qr + 8]       = gelu_f(d[j][2]);
        sZ[(nn + 1) * 68 + gm + qr + 8] = gelu_f(d[j][3]);
    }
    __syncthreads();
    float* yb = g_y + ((size_t)b * H_ + h) * L_;
    #pragma unroll
    for (int idx = tid; idx < 2048; idx += 256) {
        int col = idx >> 4, t4 = (idx & 15) << 2;
        float4 v = *reinterpret_cast<const float4*>(sZ + col * 68 + t4);
        *reinterpret_cast<float4*>(yb + col * TC + t4) = v;
    }
}

// ---------------------------------------------------------------------------
// GLU via mma.sync tf32, v2: 2 blocks/SM, register-resident GLU epilogue.
// Block = (chan-half cc, b, 64-token tile); grid 2048, cc fastest.
// sW [128 rows][132]: rows 0..63 = a-channels cc*64.., 64..127 = their gates.
// sY [128 k][72]: 64-token y tile. Warp (wr=wid&3, wc=wid>>2):
//   mt=0 -> a-rows 16wr..+15, mt=1 -> gate rows 64+16wr..; cols 32wc..+31.
// d[0]/d[1] frags are (a, gate) pairs for the SAME channel -> GLU in regs,
// shfl-reduce over qc, atomicAdd. No Z round-trip, no extra syncs.
// ---------------------------------------------------------------------------
#define SW_S 132
#define SY_S 72
#define SY_OFF 67584                      /* 128*132*4 */
#define GLU_SMEM 104448                   /* + 128*72*4 */

__global__ void __launch_bounds__(256, 2) glu_mma_kernel(const float* __restrict__ out_w,
                                                         const float* __restrict__ out_b) {
    extern __shared__ char smem[];
    uint32_t* sW = reinterpret_cast<uint32_t*>(smem);
    uint32_t* sY = reinterpret_cast<uint32_t*>(smem + SY_OFF);
    int tid = threadIdx.x;
    int wid = tid >> 5, lane = tid & 31;
    int qr = lane >> 2, qc = lane & 3;
    int bidx = blockIdx.x;
    int cc = bidx & 1;                    // channel half
    int tt = bidx >> 1;
    int b = tt >> 7, l0 = (tt & 127) << 6;
    int gbase = cc << 6;

    // ---- stage W half (64 a-rows + 64 gate rows) as tf32 ----
    #pragma unroll
    for (int m = tid; m < 4096; m += 256) {
        int row = m >> 5, c4 = (m & 31) << 2;
        int g = gbase + row + ((row & 64) ? 64 : 0);    // a: g, gate: 128+g-64
        float4 v = *reinterpret_cast<const float4*>(out_w + (size_t)g * H_ + c4);
        uint4 u = make_uint4(to_tf32(v.x), to_tf32(v.y), to_tf32(v.z), to_tf32(v.w));
        *reinterpret_cast<uint4*>(sW + row * SW_S + c4) = u;
    }
    // ---- stage Y tile (64 tokens) as tf32 ----
    const float* yb = g_y + (size_t)b * H_ * L_ + l0;
    #pragma unroll
    for (int m = tid; m < 2048; m += 256) {
        int hh = m >> 4, t4 = (m & 15) << 2;
        float4 v = *reinterpret_cast<const float4*>(yb + (size_t)hh * L_ + t4);
        uint4 u = make_uint4(to_tf32(v.x), to_tf32(v.y), to_tf32(v.z), to_tf32(v.w));
        *reinterpret_cast<uint4*>(sY + hh * SY_S + t4) = u;
    }
    __syncthreads();

    int gm = (wid & 3) << 4, nh = (wid >> 2) << 5;
    float d[2][4][4];
    #pragma unroll
    for (int mt = 0; mt < 2; ++mt)
        #pragma unroll
        for (int j = 0; j < 4; ++j)
            #pragma unroll
            for (int q = 0; q < 4; ++q) d[mt][j][q] = 0.f;

    const uint32_t* wA = sW + (gm + qr) * SW_S + qc;
    #pragma unroll 4
    for (int s = 0; s < 16; ++s) {
        int kk = s << 3;
        uint32_t a[2][4];
        {
            const uint32_t* wp = wA + kk;
            a[0][0] = wp[0]; a[0][1] = wp[8 * SW_S];
            a[0][2] = wp[4]; a[0][3] = wp[8 * SW_S + 4];
            const uint32_t* wq = wp + 64 * SW_S;
            a[1][0] = wq[0]; a[1][1] = wq[8 * SW_S];
            a[1][2] = wq[4]; a[1][3] = wq[8 * SW_S + 4];
        }
        const uint32_t* y0 = sY + (kk + qc) * SY_S + nh + qr;
        #pragma unroll
        for (int j = 0; j < 4; ++j) {
            uint32_t bb[2] = { y0[j << 3], y0[4 * SY_S + (j << 3)] };
            mma_tf32(d[0][j], a[0], bb);
            mma_tf32(d[1][j], a[1], bb);
        }
    }

    // ---- register GLU + pool ----
    int ga  = gbase + gm + qr;            // channel for acc rows qr
    int ga8 = ga + 8;                     // channel for acc rows qr+8
    float bA0 = out_b[ga],  bG0 = out_b[128 + ga];
    float bA8 = out_b[ga8], bG8 = out_b[128 + ga8];
    float s0 = 0.f, s8 = 0.f;
    #pragma unroll
    for (int j = 0; j < 4; ++j) {
        s0 += (d[0][j][0] + bA0) * sigm(d[1][j][0] + bG0);
        s0 += (d[0][j][1] + bA0) * sigm(d[1][j][1] + bG0);
        s8 += (d[0][j][2] + bA8) * sigm(d[1][j][2] + bG8);
        s8 += (d[0][j][3] + bA8) * sigm(d[1][j][3] + bG8);
    }
    s0 += __shfl_xor_sync(0xffffffffu, s0, 1);
    s0 += __shfl_xor_sync(0xffffffffu, s0, 2);
    s8 += __shfl_xor_sync(0xffffffffu, s8, 1);
    s8 += __shfl_xor_sync(0xffffffffu, s8, 2);
    if (qc == 0) {
        atomicAdd(&g_pooled[b * H_ + ga],  s0);
        atomicAdd(&g_pooled[b * H_ + ga8], s8);
    }
}

// ---------------------------------------------------------------------------
// Decode: out[b] = (pooled_sum[b,:]/L) . dec_w + dec_b
// ---------------------------------------------------------------------------
__global__ void decode_kernel(const float* __restrict__ dec_w,
                              const float* __restrict__ dec_b,
                              float* __restrict__ out) {
    int wid = threadIdx.x >> 5, lane = threadIdx.x & 31;
    int b = wid;
    float p = 0.f;
    #pragma unroll
    for (int i = 0; i < 4; i++) {
        int h = lane + 32 * i;
        p += g_pooled[b * H_ + h] * dec_w[h];
    }
    p += __shfl_xor_sync(0xffffffffu, p, 16);
    p += __shfl_xor_sync(0xffffffffu, p, 8);
    p += __shfl_xor_sync(0xffffffffu, p, 4);
    p += __shfl_xor_sync(0xffffffffu, p, 2);
    p += __shfl_xor_sync(0xffffffffu, p, 1);
    if (lane == 0) out[b] = p * (1.f / (float)L_) + dec_b[0];
}

// ---------------------------------------------------------------------------
extern "C" void kernel_launch(void* const* d_in, const int* in_sizes, int n_in,
                              void* d_out, int out_size) {
    const float* x      = (const float*)d_in[0];
    const float* enc_w  = (const float*)d_in[1];
    const float* enc_b  = (const float*)d_in[2];
    const float* log_dt = (const float*)d_in[3];
    const float* log_A  = (const float*)d_in[4];
    const float* A_im   = (const float*)d_in[5];
    const float* C_re   = (const float*)d_in[6];
    const float* C_im   = (const float*)d_in[7];
    const float* D      = (const float*)d_in[8];
    const float* out_w  = (const float*)d_in[9];
    const float* out_b  = (const float*)d_in[10];
    const float* dec_w  = (const float*)d_in[11];
    const float* dec_b  = (const float*)d_in[12];
    float* out = (float*)d_out;

    cudaFuncSetAttribute(ssm_mma_kernel, cudaFuncAttributeMaxDynamicSharedMemorySize,
                         SSM_SMEM);
    cudaFuncSetAttribute(glu_mma_kernel, cudaFuncAttributeMaxDynamicSharedMemorySize,
                         GLU_SMEM);

    setup2_kernel<<<128, 64>>>(log_dt, log_A, A_im, C_re, C_im, D);
    ssm_mma_kernel<<<1024, 256, SSM_SMEM>>>(x, enc_w, enc_b);
    glu_mma_kernel<<<2048, 256, GLU_SMEM>>>(out_w, out_b);
    decode_kernel<<<1, 256>>>(dec_w, dec_b, out);
}

// round 17
// speedup vs baseline: 2.9179x; 1.1164x over previous
#include <cuda_runtime.h>
#include <cstdint>

#define B_ 8
#define L_ 8192
#define H_ 128
#define N_ 32
#define G_ 256   /* 2H */
#define TC 64    /* chunk length */
#define J_ 128   /* chunks per sequence */

typedef unsigned long long ull;

// Scratch (static __device__ arrays: no allocation anywhere)
__device__ float2 g_wT[H_ * N_];                        // w^64
__device__ __align__(16) float g_A1t[(size_t)H_ * TC * TC];      // finals matrix [h][r][k]
__device__ __align__(16) float g_A2t[(size_t)H_ * TC * 2 * TC];  // [Tri+D | V]   [h][t][k]
__device__ float  g_y[(size_t)B_ * H_ * L_];            // post-GELU activations (B,H,L)
__device__ float  g_pooled[B_ * H_];

__device__ __forceinline__ float gelu_f(float yv) {
    float c_ = fmaf(0.044715f, yv * yv, 1.f);
    float q_ = -1.5957691216f * yv * c_;
    return __fdividef(yv, 1.f + __expf(q_));            // yv * sigmoid(2*0.79788*yv*c)
}
__device__ __forceinline__ float sigm(float v) {
    return __fdividef(1.f, 1.f + __expf(-v));
}
__device__ __forceinline__ uint32_t to_tf32(float f) {
    uint32_t u; asm("cvt.rna.tf32.f32 %0, %1;" : "=r"(u) : "f"(f)); return u;
}
__device__ __forceinline__ void mma_tf32(float* d, const uint32_t* a, const uint32_t* b) {
    asm volatile(
        "mma.sync.aligned.m16n8k8.row.col.f32.tf32.tf32.f32 "
        "{%0,%1,%2,%3}, {%4,%5,%6,%7}, {%8,%9}, {%0,%1,%2,%3};"
        : "+f"(d[0]), "+f"(d[1]), "+f"(d[2]), "+f"(d[3])
        : "r"(a[0]), "r"(a[1]), "r"(a[2]), "r"(a[3]), "r"(b[0]), "r"(b[1]));
}

// ---------------------------------------------------------------------------
// Setup (merged): per-head SSM params, power table, A1t/A2t, w^64, pooled=0.
// 128 blocks (head) x 64 threads.
// ---------------------------------------------------------------------------
__global__ void setup2_kernel(const float* __restrict__ log_dt,
                              const float* __restrict__ log_A_real,
                              const float* __restrict__ A_imag,
                              const float* __restrict__ C_re,
                              const float* __restrict__ C_im,
                              const float* __restrict__ D) {
    __shared__ float wr[TC + 1][32], wim[TC + 1][32];
    __shared__ float skr[32], ski[32], kap[TC];
    int h = blockIdx.x, t = threadIdx.x;
    if (t < 32) {
        int i = h * N_ + t;
        float dt = expf(log_dt[h]);
        float ar = -expf(log_A_real[i]);
        float ai = A_imag[i];
        float er = expf(dt * ar);
        float si, co;
        sincosf(dt * ai, &si, &co);
        float w_r = er * co, w_i = er * si;     // w = exp(dt*A)
        float inv = 1.f / (ar * ar + ai * ai);
        float dr = w_r - 1.f;
        float qr_ = (dr * ar + w_i * ai) * inv; // (w-1)/A
        float qi_ = (w_i * ar - dr * ai) * inv;
        float cr = C_re[i], ci = C_im[i];
        skr[t] = 2.f * (cr * qr_ - ci * qi_);   // k = 2*C*(w-1)/A
        ski[t] = 2.f * (cr * qi_ + ci * qr_);
        float pr = 1.f, pi = 0.f;
        for (int d = 0; d <= TC; ++d) {
            wr[d][t] = pr; wim[d][t] = pi;
            float nr = pr * w_r - pi * w_i;
            pi = pr * w_i + pi * w_r;
            pr = nr;
        }
        g_wT[i] = make_float2(wr[TC][t], wim[TC][t]);   // w^64 from the table
    }
    if (h < 16) g_pooled[h * 64 + t] = 0.f;
    __syncthreads();
    {   // kappa[t] = Re(sum_n k_n w_n^t)
        float s = 0.f;
        #pragma unroll
        for (int n = 0; n < 32; ++n)
            s += skr[n] * wr[t][n] - ski[n] * wim[t][n];
        kap[t] = s;
    }
    __syncthreads();
    float Dh = D[h];
    for (int idx = t; idx < TC * TC; idx += 64) {
        int r = idx >> 6, k = idx & 63;
        g_A1t[(size_t)h * 4096 + idx] = (r < 32) ? wr[63 - k][r] : wim[63 - k][r - 32];
    }
    for (int idx = t; idx < TC * 2 * TC; idx += 64) {
        int tt = idx >> 7, k = idx & 127;
        float v;
        if (k < 64)      v = (tt > k) ? kap[tt - k] : (tt == k ? kap[0] + Dh : 0.f);
        else if (k < 96) { int n = k - 64; v = skr[n] * wr[tt + 1][n] - ski[n] * wim[tt + 1][n]; }
        else             { int n = k - 96; v = -(skr[n] * wim[tt + 1][n] + ski[n] * wr[tt + 1][n]); }
        g_A2t[(size_t)h * 8192 + idx] = v;
    }
}

// ---------------------------------------------------------------------------
// Fused SSM via mma.sync tf32, v2: 100 KB smem -> 2 blocks/SM.
// Regions (by liveness):
//   R   @0      (34816 B, stride 68): sA1 -> sFC (F/carries, fp32) -> sZ
//   sA2 @34816  (33792 B, stride 132): A2t tf32 [t][k]
//   sB  @68608  (33792 B, stride 132): U tf32 [k][col] -> C tf32 (overwrite)
// GEMM2 split by K: GEMM2a = Tri@U (k 0..63), transpose carries into sB,
// GEMM2b += V@C (k 64..127). Accumulators persist in registers.
// ---------------------------------------------------------------------------
#define R_S   68
#define SB_S  132
#define OFF_A2 34816
#define OFF_B  68608
#define SSM_SMEM 102400

__global__ void __launch_bounds__(256, 2) ssm_mma_kernel(const float* __restrict__ x,
                                                         const float* __restrict__ enc_w,
                                                         const float* __restrict__ enc_b) {
    extern __shared__ char smem[];
    uint32_t* sR32 = reinterpret_cast<uint32_t*>(smem);          // A1 phase
    float*    sF   = reinterpret_cast<float*>(smem);             // F/carry + sZ phase
    uint32_t* sA2  = reinterpret_cast<uint32_t*>(smem + OFF_A2); // [t][132]
    uint32_t* sB   = reinterpret_cast<uint32_t*>(smem + OFF_B);  // [k][132]
    int tid = threadIdx.x;
    int wid = tid >> 5, lane = tid & 31;
    int qr = lane >> 2, qc = lane & 3;
    int gm = (wid & 3) << 4, nh = (wid >> 2) << 6;
    int h = blockIdx.x >> 3, b = blockIdx.x & 7;

    // ---- encoder fill: U rows 0..63 of sB (tf32) ----
    float e0 = enc_w[h], e1 = enc_w[H_ + h], eb = enc_b[h];
    const float2* xb = reinterpret_cast<const float2*>(x) + (size_t)b * L_;
    #pragma unroll
    for (int m = tid; m < 8192; m += 256) {
        float2 xv = xb[m];
        float u = fmaf(e1, xv.y, fmaf(e0, xv.x, eb));
        sB[(m & 63) * SB_S + (m >> 6)] = to_tf32(u);
    }
    // ---- load A1 into R (stride 68) ----
    {
        const float* A1p = g_A1t + (size_t)h * 4096;
        #pragma unroll
        for (int m = tid; m < 4096; m += 256)
            sR32[(m >> 6) * R_S + (m & 63)] = to_tf32(A1p[m]);
    }
    __syncthreads();

    // ---- GEMM1: F = A1 @ U (K=64) ----
    float d[8][4];
    #pragma unroll
    for (int j = 0; j < 8; ++j)
        #pragma unroll
        for (int q = 0; q < 4; ++q) d[j][q] = 0.f;
    {
        const uint32_t* wA = sR32 + (gm + qr) * R_S + qc;
        #pragma unroll
        for (int s = 0; s < 8; ++s) {
            int kk = s << 3;
            uint32_t a[4];
            const uint32_t* wp = wA + kk;
            a[0] = wp[0]; a[1] = wp[8 * R_S]; a[2] = wp[4]; a[3] = wp[8 * R_S + 4];
            const uint32_t* y0 = sB + (kk + qc) * SB_S + nh + qr;
            #pragma unroll
            for (int j = 0; j < 8; ++j) {
                uint32_t bb[2] = { y0[j << 3], y0[4 * SB_S + (j << 3)] };
                mma_tf32(d[j], a, bb);
            }
        }
    }
    __syncthreads();            // A1 reads done -> R becomes sFC

    // ---- store F -> sF[col][r] ----
    #pragma unroll
    for (int j = 0; j < 8; ++j) {
        int nn = nh + (j << 3) + (qc << 1);
        sF[nn * R_S + gm + qr]           = d[j][0];
        sF[(nn + 1) * R_S + gm + qr]     = d[j][1];
        sF[nn * R_S + gm + qr + 8]       = d[j][2];
        sF[(nn + 1) * R_S + gm + qr + 8] = d[j][3];
    }
    __syncthreads();

    // ---- load A2 while warp 0 runs the carry chain (fp32, in sF) ----
    {
        const float* A2p = g_A2t + (size_t)h * 8192;
        #pragma unroll
        for (int m = tid; m < 8192; m += 256)
            sA2[(m >> 7) * SB_S + (m & 127)] = to_tf32(A2p[m]);
    }
    if (tid < 32) {             // c(j) = w^64 c(j-1) + f(j-1), overwrite F->C
        float2 wT = g_wT[h * N_ + tid];
        float wTx = wT.x, wTy = wT.y;
        float cr = 0.f, ci = 0.f;
        float* fr0 = sF + tid;
        float* fi0 = sF + 32 + tid;
        for (int j = 0; j < J_; j += 4) {
            float fr[4], fi[4];
            #pragma unroll
            for (int q = 0; q < 4; ++q) {
                fr[q] = fr0[(j + q) * R_S];
                fi[q] = fi0[(j + q) * R_S];
            }
            #pragma unroll
            for (int q = 0; q < 4; ++q) {
                fr0[(j + q) * R_S] = cr;
                fi0[(j + q) * R_S] = ci;
                float nr = fmaf(wTx, cr, fmaf(-wTy, ci, fr[q]));
                ci = fmaf(wTy, cr, fmaf(wTx, ci, fi[q]));
                cr = nr;
            }
        }
    }
    __syncthreads();

    // ---- GEMM2a: acc = Tri @ U  (A2 k-cols 0..63, B = U still in sB) ----
    #pragma unroll
    for (int j = 0; j < 8; ++j)
        #pragma unroll
        for (int q = 0; q < 4; ++q) d[j][q] = 0.f;
    {
        const uint32_t* wA = sA2 + (gm + qr) * SB_S + qc;
        #pragma unroll
        for (int s = 0; s < 8; ++s) {
            int kk = s << 3;
            uint32_t a[4];
            const uint32_t* wp = wA + kk;
            a[0] = wp[0]; a[1] = wp[8 * SB_S]; a[2] = wp[4]; a[3] = wp[8 * SB_S + 4];
            const uint32_t* y0 = sB + (kk + qc) * SB_S + nh + qr;
            #pragma unroll
            for (int j = 0; j < 8; ++j) {
                uint32_t bb[2] = { y0[j << 3], y0[4 * SB_S + (j << 3)] };
                mma_tf32(d[j], a, bb);
            }
        }
    }
    __syncthreads();            // U reads done -> sB becomes C

    // ---- transpose carries into sB (tf32): sB[n][col] = sF[col][n] ----
    #pragma unroll
    for (int m = tid; m < 8192; m += 256) {
        int n = m >> 7, col = m & 127;
        sB[n * SB_S + col] = to_tf32(sF[col * R_S + n]);
    }
    __syncthreads();

    // ---- GEMM2b: acc += V @ C  (A2 k-cols 64..127) ----
    {
        const uint32_t* wA = sA2 + (gm + qr) * SB_S + 64 + qc;
        #pragma unroll
        for (int s = 0; s < 8; ++s) {
            int kk = s << 3;
            uint32_t a[4];
            const uint32_t* wp = wA + kk;
            a[0] = wp[0]; a[1] = wp[8 * SB_S]; a[2] = wp[4]; a[3] = wp[8 * SB_S + 4];
            const uint32_t* y0 = sB + (kk + qc) * SB_S + nh + qr;
            #pragma unroll
            for (int j = 0; j < 8; ++j) {
                uint32_t bb[2] = { y0[j << 3], y0[4 * SB_S + (j << 3)] };
                mma_tf32(d[j], a, bb);
            }
        }
    }

    // ---- GELU -> sZ (R region, stride 68), then coalesced STG ----
    float* sZ = sF;
    #pragma unroll
    for (int j = 0; j < 8; ++j) {
        int nn = nh + (j << 3) + (qc << 1);
        sZ[nn * R_S + gm + qr]           = gelu_f(d[j][0]);
        sZ[(nn + 1) * R_S + gm + qr]     = gelu_f(d[j][1]);
        sZ[nn * R_S + gm + qr + 8]       = gelu_f(d[j][2]);
        sZ[(nn + 1) * R_S + gm + qr + 8] = gelu_f(d[j][3]);
    }
    __syncthreads();
    float* yb = g_y + ((size_t)b * H_ + h) * L_;
    #pragma unroll
    for (int idx = tid; idx < 2048; idx += 256) {
        int col = idx >> 4, t4 = (idx & 15) << 2;
        float4 v = *reinterpret_cast<const float4*>(sZ + col * R_S + t4);
        *reinterpret_cast<float4*>(yb + col * TC + t4) = v;
    }
}

// ---------------------------------------------------------------------------
// GLU via mma.sync tf32 (proven R14 kernel, unchanged): 2 blocks/SM,
// register-resident GLU epilogue.
// ---------------------------------------------------------------------------
#define SW_S 132
#define SY_S 72
#define SY_OFF 67584                      /* 128*132*4 */
#define GLU_SMEM 104448                   /* + 128*72*4 */

__global__ void __launch_bounds__(256, 2) glu_mma_kernel(const float* __restrict__ out_w,
                                                         const float* __restrict__ out_b) {
    extern __shared__ char smem[];
    uint32_t* sW = reinterpret_cast<uint32_t*>(smem);
    uint32_t* sY = reinterpret_cast<uint32_t*>(smem + SY_OFF);
    int tid = threadIdx.x;
    int wid = tid >> 5, lane = tid & 31;
    int qr = lane >> 2, qc = lane & 3;
    int bidx = blockIdx.x;
    int cc = bidx & 1;                    // channel half
    int tt = bidx >> 1;
    int b = tt >> 7, l0 = (tt & 127) << 6;
    int gbase = cc << 6;

    #pragma unroll
    for (int m = tid; m < 4096; m += 256) {
        int row = m >> 5, c4 = (m & 31) << 2;
        int g = gbase + row + ((row & 64) ? 64 : 0);    // a: g, gate: 128+g-64
        float4 v = *reinterpret_cast<const float4*>(out_w + (size_t)g * H_ + c4);
        uint4 u = make_uint4(to_tf32(v.x), to_tf32(v.y), to_tf32(v.z), to_tf32(v.w));
        *reinterpret_cast<uint4*>(sW + row * SW_S + c4) = u;
    }
    const float* yb = g_y + (size_t)b * H_ * L_ + l0;
    #pragma unroll
    for (int m = tid; m < 2048; m += 256) {
        int hh = m >> 4, t4 = (m & 15) << 2;
        float4 v = *reinterpret_cast<const float4*>(yb + (size_t)hh * L_ + t4);
        uint4 u = make_uint4(to_tf32(v.x), to_tf32(v.y), to_tf32(v.z), to_tf32(v.w));
        *reinterpret_cast<uint4*>(sY + hh * SY_S + t4) = u;
    }
    __syncthreads();

    int gm = (wid & 3) << 4, nh = (wid >> 2) << 5;
    float d[2][4][4];
    #pragma unroll
    for (int mt = 0; mt < 2; ++mt)
        #pragma unroll
        for (int j = 0; j < 4; ++j)
            #pragma unroll
            for (int q = 0; q < 4; ++q) d[mt][j][q] = 0.f;

    const uint32_t* wA = sW + (gm + qr) * SW_S + qc;
    #pragma unroll 4
    for (int s = 0; s < 16; ++s) {
        int kk = s << 3;
        uint32_t a[2][4];
        {
            const uint32_t* wp = wA + kk;
            a[0][0] = wp[0]; a[0][1] = wp[8 * SW_S];
            a[0][2] = wp[4]; a[0][3] = wp[8 * SW_S + 4];
            const uint32_t* wq = wp + 64 * SW_S;
            a[1][0] = wq[0]; a[1][1] = wq[8 * SW_S];
            a[1][2] = wq[4]; a[1][3] = wq[8 * SW_S + 4];
        }
        const uint32_t* y0 = sY + (kk + qc) * SY_S + nh + qr;
        #pragma unroll
        for (int j = 0; j < 4; ++j) {
            uint32_t bb[2] = { y0[j << 3], y0[4 * SY_S + (j << 3)] };
            mma_tf32(d[0][j], a[0], bb);
            mma_tf32(d[1][j], a[1], bb);
        }
    }

    // ---- register GLU + pool ----
    int ga  = gbase + gm + qr;
    int ga8 = ga + 8;
    float bA0 = out_b[ga],  bG0 = out_b[128 + ga];
    float bA8 = out_b[ga8], bG8 = out_b[128 + ga8];
    float s0 = 0.f, s8 = 0.f;
    #pragma unroll
    for (int j = 0; j < 4; ++j) {
        s0 += (d[0][j][0] + bA0) * sigm(d[1][j][0] + bG0);
        s0 += (d[0][j][1] + bA0) * sigm(d[1][j][1] + bG0);
        s8 += (d[0][j][2] + bA8) * sigm(d[1][j][2] + bG8);
        s8 += (d[0][j][3] + bA8) * sigm(d[1][j][3] + bG8);
    }
    s0 += __shfl_xor_sync(0xffffffffu, s0, 1);
    s0 += __shfl_xor_sync(0xffffffffu, s0, 2);
    s8 += __shfl_xor_sync(0xffffffffu, s8, 1);
    s8 += __shfl_xor_sync(0xffffffffu, s8, 2);
    if (qc == 0) {
        atomicAdd(&g_pooled[b * H_ + ga],  s0);
        atomicAdd(&g_pooled[b * H_ + ga8], s8);
    }
}

// ---------------------------------------------------------------------------
// Decode: out[b] = (pooled_sum[b,:]/L) . dec_w + dec_b
// ---------------------------------------------------------------------------
__global__ void decode_kernel(const float* __restrict__ dec_w,
                              const float* __restrict__ dec_b,
                              float* __restrict__ out) {
    int wid = threadIdx.x >> 5, lane = threadIdx.x & 31;
    int b = wid;
    float p = 0.f;
    #pragma unroll
    for (int i = 0; i < 4; i++) {
        int h = lane + 32 * i;
        p += g_pooled[b * H_ + h] * dec_w[h];
    }
    p += __shfl_xor_sync(0xffffffffu, p, 16);
    p += __shfl_xor_sync(0xffffffffu, p, 8);
    p += __shfl_xor_sync(0xffffffffu, p, 4);
    p += __shfl_xor_sync(0xffffffffu, p, 2);
    p += __shfl_xor_sync(0xffffffffu, p, 1);
    if (lane == 0) out[b] = p * (1.f / (float)L_) + dec_b[0];
}

// ---------------------------------------------------------------------------
extern "C" void kernel_launch(void* const* d_in, const int* in_sizes, int n_in,
                              void* d_out, int out_size) {
    const float* x      = (const float*)d_in[0];
    const float* enc_w  = (const float*)d_in[1];
    const float* enc_b  = (const float*)d_in[2];
    const float* log_dt = (const float*)d_in[3];
    const float* log_A  = (const float*)d_in[4];
    const float* A_im   = (const float*)d_in[5];
    const float* C_re   = (const float*)d_in[6];
    const float* C_im   = (const float*)d_in[7];
    const float* D      = (const float*)d_in[8];
    const float* out_w  = (const float*)d_in[9];
    const float* out_b  = (const float*)d_in[10];
    const float* dec_w  = (const float*)d_in[11];
    const float* dec_b  = (const float*)d_in[12];
    float* out = (float*)d_out;

    cudaFuncSetAttribute(ssm_mma_kernel, cudaFuncAttributeMaxDynamicSharedMemorySize,
                         SSM_SMEM);
    cudaFuncSetAttribute(glu_mma_kernel, cudaFuncAttributeMaxDynamicSharedMemorySize,
                         GLU_SMEM);

    setup2_kernel<<<128, 64>>>(log_dt, log_A, A_im, C_re, C_im, D);
    ssm_mma_kernel<<<1024, 256, SSM_SMEM>>>(x, enc_w, enc_b);
    glu_mma_kernel<<<2048, 256, GLU_SMEM>>>(out_w, out_b);
    decode_kernel<<<1, 256>>>(dec_w, dec_b, out);
}